// round 9
// baseline (speedup 1.0000x reference)
#include <cuda_runtime.h>
#include <cuda_bf16.h>
#include <cstdint>
#include <math.h>

// Problem constants
constexpr int BATCH = 2;
constexpr int SEQ   = 2048;
constexpr int EMB   = 1024;
constexpr int NH    = 16;
constexpr int HD    = 64;
constexpr int HD2   = 32;
constexpr int M_TOT = BATCH * SEQ;   // 4096

// GEMM tiling (mma.sync, 3-segment extended-K:  A3=[hi|hi|lo], B3=[hi|lo|hi])
constexpr int TM  = 128;
constexpr int TN  = 128;
constexpr int K3  = 3 * EMB;          // 3072
constexpr int KC  = 64;               // bf16 per chunk = 128 B rows
constexpr int NCH = K3 / KC;          // 48
constexpr int STAGE_BYTES = 2 * TM * 128;          // A tile + B tile = 32 KB
constexpr int NSTAGE = 3;
constexpr uint32_t GEMM_SMEM = NSTAGE * STAGE_BYTES;   // 96 KB

// Flash smem layout (bytes)
constexpr uint32_t FQHI = 0;           // 16 KB (reused as O-reduce buffer at end)
constexpr uint32_t FQLO = 16384;
constexpr uint32_t FKV  = 32768;       // 2 stages x 32 KB
constexpr uint32_t FSTG = 32768;       // within stage: KHI 0, KLO 8K, VHI 16K, VLO 24K
constexpr uint32_t FLSM = 98304;       // 512 B for l
constexpr uint32_t FLASH_SMEM = 98304 + 512;

// ---------------------------------------------------------------------------
// Scratch (device globals -- no runtime allocation allowed)
// ---------------------------------------------------------------------------
__device__ float g_adapt[BATCH * EMB];

__device__ __nv_bfloat16 g_x3[(size_t)M_TOT * K3];      // [m][hi | hi | lo]
__device__ __nv_bfloat16 g_a3[(size_t)M_TOT * K3];      // attention out (written by flash)
__device__ __nv_bfloat16 g_w3[4][(size_t)EMB * K3];     // transposed [n][hi | lo | hi]

__device__ __nv_bfloat16 g_qhi[(size_t)BATCH * NH * SEQ * HD];  // [bh][s][d]
__device__ __nv_bfloat16 g_qlo[(size_t)BATCH * NH * SEQ * HD];
__device__ __nv_bfloat16 g_khi[(size_t)BATCH * NH * SEQ * HD];
__device__ __nv_bfloat16 g_klo[(size_t)BATCH * NH * SEQ * HD];
__device__ __nv_bfloat16 g_vthi[(size_t)BATCH * NH * HD * SEQ]; // [bh][d][s]
__device__ __nv_bfloat16 g_vtlo[(size_t)BATCH * NH * HD * SEQ];

// ---------------------------------------------------------------------------
// Helpers
// ---------------------------------------------------------------------------
__device__ __forceinline__ uint32_t smem_u32(const void* p) {
    uint32_t a;
    asm("{ .reg .u64 t; cvta.to.shared.u64 t, %1; cvt.u32.u64 %0, t; }" : "=r"(a) : "l"(p));
    return a;
}
#define SWZ128(off) ((off) ^ (((off) >> 3) & 0x70))

__device__ __forceinline__ void cp16(uint32_t d, const void* g) {
    asm volatile("cp.async.cg.shared.global [%0], [%1], 16;" :: "r"(d), "l"(g));
}
__device__ __forceinline__ void ldm4(uint32_t* f, uint32_t addr) {
    asm volatile("ldmatrix.sync.aligned.m8n8.x4.shared.b16 {%0,%1,%2,%3}, [%4];"
        : "=r"(f[0]), "=r"(f[1]), "=r"(f[2]), "=r"(f[3]) : "r"(addr));
}
__device__ __forceinline__ void mma16816(float* c, const uint32_t* a, uint32_t b0, uint32_t b1) {
    asm volatile("mma.sync.aligned.m16n8k16.row.col.f32.bf16.bf16.f32 "
        "{%0,%1,%2,%3}, {%4,%5,%6,%7}, {%8,%9}, {%0,%1,%2,%3};"
        : "+f"(c[0]), "+f"(c[1]), "+f"(c[2]), "+f"(c[3])
        : "r"(a[0]), "r"(a[1]), "r"(a[2]), "r"(a[3]), "r"(b0), "r"(b1));
}
__device__ __forceinline__ float fast_ex2(float x) {
    float y; asm("ex2.approx.f32 %0, %1;" : "=f"(y) : "f"(x)); return y;
}
__device__ __forceinline__ uint32_t pack_bf16x2(__nv_bfloat16 lo, __nv_bfloat16 hi) {
    __nv_bfloat162 t; t.x = lo; t.y = hi;
    uint32_t r;
    memcpy(&r, &t, 4);
    return r;
}

// ---------------------------------------------------------------------------
// Kernel: adapt
// ---------------------------------------------------------------------------
__global__ void adapt_kernel(const float* __restrict__ xi,
                             const float* __restrict__ ew1, const float* __restrict__ eb1,
                             const float* __restrict__ lng, const float* __restrict__ lnb,
                             const float* __restrict__ ew2, const float* __restrict__ eb2,
                             const float* __restrict__ gate)
{
    int b = threadIdx.x;
    if (b >= BATCH) return;
    float x[HD2];
    float xv = xi[b];
    float mu = 0.f;
#pragma unroll
    for (int i = 0; i < HD2; ++i) { x[i] = xv * ew1[i] + eb1[i]; mu += x[i]; }
    mu *= (1.0f / HD2);
    float var = 0.f;
#pragma unroll
    for (int i = 0; i < HD2; ++i) { float d = x[i] - mu; var += d * d; }
    var *= (1.0f / HD2);
    float rs = rsqrtf(var + 1e-5f);
#pragma unroll
    for (int i = 0; i < HD2; ++i) {
        float xn = (x[i] - mu) * rs * lng[i] + lnb[i];
        x[i] = 0.5f * xn * (1.f + erff(xn * 0.70710678118654752f));
    }
    float sg[NH];
#pragma unroll
    for (int h = 0; h < NH; ++h) sg[h] = 1.f / (1.f + expf(-gate[h]));
    for (int d = 0; d < HD; ++d) {
        float xe = eb2[d];
#pragma unroll
        for (int i = 0; i < HD2; ++i) xe += x[i] * ew2[i * HD + d];
#pragma unroll
        for (int h = 0; h < NH; ++h)
            g_adapt[b * EMB + h * HD + d] = 1.f + sg[h] * xe;
    }
}

// ---------------------------------------------------------------------------
// Kernel: fp32 [M,1024] -> bf16 [M, 3072] = [hi | hi | lo]
// ---------------------------------------------------------------------------
__global__ void __launch_bounds__(256)
split3_kernel(const float* __restrict__ in, __nv_bfloat16* __restrict__ out3, int n)
{
    int i = blockIdx.x * 256 + threadIdx.x;
    if (i < n) {
        int m = i >> 10, k = i & 1023;
        float x = in[i];
        __nv_bfloat16 h = __float2bfloat16(x);
        __nv_bfloat16 l = __float2bfloat16(x - __bfloat162float(h));
        size_t base = (size_t)m * K3 + k;
        out3[base]           = h;
        out3[base + EMB]     = h;
        out3[base + 2 * EMB] = l;
    }
}

// ---------------------------------------------------------------------------
// Kernel: W[K,N] fp32 -> transposed bf16 [N, 3072] = [hi | lo | hi]
// ---------------------------------------------------------------------------
__global__ void __launch_bounds__(256)
wsplit3_kernel(const float* __restrict__ W, __nv_bfloat16* __restrict__ out3)
{
    __shared__ float t[32][33];
    int n0 = blockIdx.x * 32, k0 = blockIdx.y * 32;
    int tx = threadIdx.x, ty = threadIdx.y;   // (32, 8)
#pragma unroll
    for (int i = 0; i < 32; i += 8)
        t[ty + i][tx] = W[(size_t)(k0 + ty + i) * EMB + n0 + tx];
    __syncthreads();
#pragma unroll
    for (int i = 0; i < 32; i += 8) {
        float x = t[tx][ty + i];              // k=k0+tx, n=n0+ty+i
        __nv_bfloat16 h = __float2bfloat16(x);
        __nv_bfloat16 l = __float2bfloat16(x - __bfloat162float(h));
        size_t base = (size_t)(n0 + ty + i) * K3 + k0 + tx;
        out3[base]           = h;
        out3[base + EMB]     = l;
        out3[base + 2 * EMB] = h;
    }
}

// ---------------------------------------------------------------------------
// Kernel: mma.sync bf16 GEMM  C[M,N] = A3[M,K3] * B3[N,K3]^T + bias, fused epi.
// 3-stage cp.async pipeline. Modes as before.
// ---------------------------------------------------------------------------
__global__ void __launch_bounds__(256)
gemm_mma(const __nv_bfloat16* __restrict__ A3, const __nv_bfloat16* __restrict__ B3,
         const float* __restrict__ bias, float* __restrict__ out, int mode)
{
    extern __shared__ __align__(1024) char smem[];
    const uint32_t sb = smem_u32(smem);
    const int tid  = threadIdx.x;
    const int lane = tid & 31;
    const int wid  = tid >> 5;
    const int wm   = wid >> 1;        // 0..3
    const int wn   = wid & 1;         // 0..1
    const int m0 = blockIdx.y * TM;
    const int n0 = blockIdx.x * TN;

    const __nv_bfloat16* Ab = A3 + (size_t)m0 * K3;
    const __nv_bfloat16* Bb = B3 + (size_t)n0 * K3;

    float c[2][8][4];
#pragma unroll
    for (int a = 0; a < 2; ++a)
#pragma unroll
        for (int b = 0; b < 8; ++b)
#pragma unroll
            for (int d = 0; d < 4; ++d) c[a][b][d] = 0.f;

#define PREFETCH(kc)                                                                   \
    do {                                                                               \
        uint32_t st = sb + ((kc) % NSTAGE) * STAGE_BYTES;                              \
        _Pragma("unroll")                                                              \
        for (int i = 0; i < 4; ++i) {                                                  \
            int idx = tid + i * 256;                                                   \
            int r = idx >> 3, u = idx & 7;                                             \
            cp16(st + SWZ128(r * 128 + u * 16), Ab + (size_t)r * K3 + (kc) * KC + u * 8); \
            cp16(st + TM * 128 + SWZ128(r * 128 + u * 16),                             \
                 Bb + (size_t)r * K3 + (kc) * KC + u * 8);                             \
        }                                                                              \
        asm volatile("cp.async.commit_group;");                                        \
    } while (0)

    PREFETCH(0);
    PREFETCH(1);

    for (int kc = 0; kc < NCH; ++kc) {
        if (kc == NCH - 1)
            asm volatile("cp.async.wait_group 0;");
        else
            asm volatile("cp.async.wait_group 1;");
        __syncthreads();
        if (kc + 2 < NCH) PREFETCH(kc + 2);

        const uint32_t sA = sb + (kc % NSTAGE) * STAGE_BYTES;
        const uint32_t sB = sA + TM * 128;
        const int rr = lane & 15;

#pragma unroll
        for (int ks = 0; ks < 4; ++ks) {
            const int uu = 2 * ks + (lane >> 4);
            uint32_t afr[2][4], bfr[4][4];
#pragma unroll
            for (int mt = 0; mt < 2; ++mt)
                ldm4(afr[mt], sA + SWZ128((wm * 32 + mt * 16 + rr) * 128 + uu * 16));
#pragma unroll
            for (int ng = 0; ng < 4; ++ng)
                ldm4(bfr[ng], sB + SWZ128((wn * 64 + ng * 16 + rr) * 128 + uu * 16));
#pragma unroll
            for (int mt = 0; mt < 2; ++mt)
#pragma unroll
                for (int ng = 0; ng < 4; ++ng) {
                    mma16816(c[mt][ng * 2],     afr[mt], bfr[ng][0], bfr[ng][2]);
                    mma16816(c[mt][ng * 2 + 1], afr[mt], bfr[ng][1], bfr[ng][3]);
                }
        }
    }
#undef PREFETCH
    __syncthreads();

    // ---------------- epilogues ----------------
    if (mode == 2) {
        // V: stage transposed bf16 hi/lo in smem, then coalesced store to [bh][d][s]
#pragma unroll
        for (int mt = 0; mt < 2; ++mt) {
            int mrow = wm * 32 + mt * 16 + (lane >> 2);
#pragma unroll
            for (int nt = 0; nt < 8; ++nt) {
                int nl = wn * 64 + nt * 8 + (lane & 3) * 2;
                float b0 = bias[n0 + nl], b1 = bias[n0 + nl + 1];
#pragma unroll
                for (int half = 0; half < 2; ++half) {
                    int ml = mrow + half * 8;
                    float v0 = c[mt][nt][half * 2] + b0;
                    float v1 = c[mt][nt][half * 2 + 1] + b1;
                    __nv_bfloat16 h0 = __float2bfloat16(v0);
                    __nv_bfloat16 h1 = __float2bfloat16(v1);
                    __nv_bfloat16 l0 = __float2bfloat16(v0 - __bfloat162float(h0));
                    __nv_bfloat16 l1 = __float2bfloat16(v1 - __bfloat162float(h1));
                    *(__nv_bfloat16*)(smem + nl * 256 + ml * 2) = h0;
                    *(__nv_bfloat16*)(smem + (nl + 1) * 256 + ml * 2) = h1;
                    *(__nv_bfloat16*)(smem + 32768 + nl * 256 + ml * 2) = l0;
                    *(__nv_bfloat16*)(smem + 32768 + (nl + 1) * 256 + ml * 2) = l1;
                }
            }
        }
        __syncthreads();
        int bq = m0 >> 11, sq = m0 & 2047;
        int hbase = n0 >> 6;
        for (int cidx = tid; cidx < 2048; cidx += 256) {
            int nn = cidx >> 4, mc = cidx & 15;
            uint4 hv = *(uint4*)(smem + nn * 256 + mc * 16);
            uint4 lv = *(uint4*)(smem + 32768 + nn * 256 + mc * 16);
            size_t o = (((size_t)(bq * NH + hbase + (nn >> 6)) * HD + (nn & 63)) * SEQ
                        + sq + mc * 8);
            *(uint4*)&g_vthi[o] = hv;
            *(uint4*)&g_vtlo[o] = lv;
        }
        return;
    }

#pragma unroll
    for (int mt = 0; mt < 2; ++mt) {
        int row0 = wm * 32 + mt * 16 + (lane >> 2);
#pragma unroll
        for (int nt = 0; nt < 8; ++nt) {
            int n = n0 + wn * 64 + nt * 8 + (lane & 3) * 2;
            float b0 = bias[n], b1 = bias[n + 1];
#pragma unroll
            for (int half = 0; half < 2; ++half) {
                int m = m0 + row0 + half * 8;
                int b = m >> 11, s = m & 2047;
                float v0 = c[mt][nt][half * 2] + b0;
                float v1 = c[mt][nt][half * 2 + 1] + b1;
                if (mode == 3) {
                    *(float2*)&out[(size_t)m * EMB + n] = make_float2(v0, v1);
                } else {
                    // Q: fold 1/8 * log2(e); K: adapt only
                    const float sc0 = (mode == 0) ? 0.18033688f : 1.0f;  // 1.442695/8
                    v0 *= g_adapt[b * EMB + n] * sc0;
                    v1 *= g_adapt[b * EMB + n + 1] * sc0;
                    __nv_bfloat16 h0 = __float2bfloat16(v0);
                    __nv_bfloat16 h1 = __float2bfloat16(v1);
                    __nv_bfloat16 l0 = __float2bfloat16(v0 - __bfloat162float(h0));
                    __nv_bfloat16 l1 = __float2bfloat16(v1 - __bfloat162float(h1));
                    int h = n >> 6, d = n & 63;
                    size_t o = ((size_t)(b * NH + h) * SEQ + s) * HD + d;
                    __nv_bfloat162 hp; hp.x = h0; hp.y = h1;
                    __nv_bfloat162 lp; lp.x = l0; lp.y = l1;
                    if (mode == 0) {
                        *(__nv_bfloat162*)&g_qhi[o] = hp;
                        *(__nv_bfloat162*)&g_qlo[o] = lp;
                    } else {
                        *(__nv_bfloat162*)&g_khi[o] = hp;
                        *(__nv_bfloat162*)&g_klo[o] = lp;
                    }
                }
            }
        }
    }
}

// ---------------------------------------------------------------------------
// Kernel: tensor-core flash attention, P kept in registers (fragment reuse).
// ---------------------------------------------------------------------------
__global__ void __launch_bounds__(256)
flash_tc()
{
    extern __shared__ __align__(1024) char smem[];
    const uint32_t sb = smem_u32(smem);
    const int tid = threadIdx.x, lane = tid & 31, wid = tid >> 5;
    const int wm = wid >> 1, wn = wid & 1;
    const int s0 = blockIdx.x * 128;
    const int h  = blockIdx.y, b = blockIdx.z;
    const int bh = b * NH + h;
    const int rr = lane & 15;

    if (tid < 128) *(float*)(smem + FLSM + tid * 4) = 0.f;

    const __nv_bfloat16* qhi = g_qhi + ((size_t)bh * SEQ + s0) * HD;
    const __nv_bfloat16* qlo = g_qlo + ((size_t)bh * SEQ + s0) * HD;
    const __nv_bfloat16* khi = g_khi + (size_t)bh * SEQ * HD;
    const __nv_bfloat16* klo = g_klo + (size_t)bh * SEQ * HD;
    const __nv_bfloat16* vth = g_vthi + (size_t)bh * HD * SEQ;
    const __nv_bfloat16* vtl = g_vtlo + (size_t)bh * HD * SEQ;

    // Q tiles (once)
#pragma unroll
    for (int i = 0; i < 4; ++i) {
        int idx = tid + i * 256;       // 0..1023
        int r = idx >> 3, u = idx & 7;
        cp16(sb + FQHI + SWZ128(r * 128 + u * 16), qhi + r * HD + u * 8);
        cp16(sb + FQLO + SWZ128(r * 128 + u * 16), qlo + r * HD + u * 8);
    }
    asm volatile("cp.async.commit_group;");

#define KVPRE(kb)                                                                       \
    do {                                                                                \
        uint32_t st = sb + FKV + ((kb) & 1) * FSTG;                                     \
        _Pragma("unroll")                                                               \
        for (int i = 0; i < 2; ++i) {                                                   \
            int idx = tid + i * 256;     /* 0..511 */                                   \
            int r = idx >> 3, u = idx & 7;                                              \
            uint32_t sw = SWZ128(r * 128 + u * 16);                                     \
            cp16(st + sw,          khi + ((size_t)(kb) * 64 + r) * HD + u * 8);         \
            cp16(st + 8192 + sw,   klo + ((size_t)(kb) * 64 + r) * HD + u * 8);         \
            cp16(st + 16384 + sw,  vth + (size_t)r * SEQ + (kb) * 64 + u * 8);          \
            cp16(st + 24576 + sw,  vtl + (size_t)r * SEQ + (kb) * 64 + u * 8);          \
        }                                                                               \
        asm volatile("cp.async.commit_group;");                                         \
    } while (0)

    KVPRE(0);

    float oc[2][8][4];
#pragma unroll
    for (int a = 0; a < 2; ++a)
#pragma unroll
        for (int f = 0; f < 8; ++f)
#pragma unroll
            for (int d = 0; d < 4; ++d) oc[a][f][d] = 0.f;
    float l_part[4] = {0.f, 0.f, 0.f, 0.f};

#pragma unroll 1
    for (int kb = 0; kb < SEQ / 64; ++kb) {
        asm volatile("cp.async.wait_group 0;");
        __syncthreads();
        if (kb + 1 < SEQ / 64) KVPRE(kb + 1);

        const uint32_t stg = sb + FKV + (kb & 1) * FSTG;

        // ---- S = Q K^T (3-term) ----
        float sc[2][4][4];
#pragma unroll
        for (int a = 0; a < 2; ++a)
#pragma unroll
            for (int f = 0; f < 4; ++f)
#pragma unroll
                for (int d = 0; d < 4; ++d) sc[a][f][d] = 0.f;

#pragma unroll
        for (int ks = 0; ks < 4; ++ks) {
            const int uu = 2 * ks + (lane >> 4);
            uint32_t aH[2][4], aL[2][4], bH[2][4], bL[2][4];
#pragma unroll
            for (int mt = 0; mt < 2; ++mt) {
                uint32_t sw = SWZ128((wm * 32 + mt * 16 + rr) * 128 + uu * 16);
                ldm4(aH[mt], sb + FQHI + sw);
                ldm4(aL[mt], sb + FQLO + sw);
            }
#pragma unroll
            for (int ng = 0; ng < 2; ++ng) {
                uint32_t sw = SWZ128((wn * 32 + ng * 16 + rr) * 128 + uu * 16);
                ldm4(bH[ng], stg + sw);
                ldm4(bL[ng], stg + 8192 + sw);
            }
#pragma unroll
            for (int mt = 0; mt < 2; ++mt)
#pragma unroll
                for (int ng = 0; ng < 2; ++ng) {
                    mma16816(sc[mt][ng * 2],     aH[mt], bH[ng][0], bH[ng][2]);
                    mma16816(sc[mt][ng * 2 + 1], aH[mt], bH[ng][1], bH[ng][3]);
                    mma16816(sc[mt][ng * 2],     aH[mt], bL[ng][0], bL[ng][2]);
                    mma16816(sc[mt][ng * 2 + 1], aH[mt], bL[ng][1], bL[ng][3]);
                    mma16816(sc[mt][ng * 2],     aL[mt], bH[ng][0], bH[ng][2]);
                    mma16816(sc[mt][ng * 2 + 1], aL[mt], bH[ng][1], bH[ng][3]);
                }
        }

        // ---- p = 2^s; pack bf16 hi/lo A-fragments directly in registers ----
        uint32_t pAh[2][4], pBh[2][4], pAl[2][4], pBl[2][4];
#pragma unroll
        for (int mt = 0; mt < 2; ++mt)
#pragma unroll
            for (int nf = 0; nf < 4; ++nf) {
                float p0 = fast_ex2(sc[mt][nf][0]);
                float p1 = fast_ex2(sc[mt][nf][1]);
                float p2 = fast_ex2(sc[mt][nf][2]);
                float p3 = fast_ex2(sc[mt][nf][3]);
                l_part[mt * 2 + 0] += p0 + p1;
                l_part[mt * 2 + 1] += p2 + p3;
                __nv_bfloat16 h0 = __float2bfloat16(p0);
                __nv_bfloat16 h1 = __float2bfloat16(p1);
                __nv_bfloat16 h2 = __float2bfloat16(p2);
                __nv_bfloat16 h3 = __float2bfloat16(p3);
                pAh[mt][nf] = pack_bf16x2(h0, h1);
                pBh[mt][nf] = pack_bf16x2(h2, h3);
                pAl[mt][nf] = pack_bf16x2(
                    __float2bfloat16(p0 - __bfloat162float(h0)),
                    __float2bfloat16(p1 - __bfloat162float(h1)));
                pBl[mt][nf] = pack_bf16x2(
                    __float2bfloat16(p2 - __bfloat162float(h2)),
                    __float2bfloat16(p3 - __bfloat162float(h3)));
            }

        // ---- O_partial += P V over this warp's 32 keys, all 64 d ----
#pragma unroll
        for (int ksp = 0; ksp < 2; ++ksp) {
            const int uu = 2 * (wn * 2 + ksp) + (lane >> 4);
            uint32_t bH[4][4], bL[4][4];
#pragma unroll
            for (int g = 0; g < 4; ++g) {
                uint32_t sw = SWZ128((g * 16 + rr) * 128 + uu * 16);
                ldm4(bH[g], stg + 16384 + sw);
                ldm4(bL[g], stg + 24576 + sw);
            }
#pragma unroll
            for (int mt = 0; mt < 2; ++mt) {
                uint32_t aH[4] = {pAh[mt][2 * ksp], pBh[mt][2 * ksp],
                                  pAh[mt][2 * ksp + 1], pBh[mt][2 * ksp + 1]};
                uint32_t aL[4] = {pAl[mt][2 * ksp], pBl[mt][2 * ksp],
                                  pAl[mt][2 * ksp + 1], pBl[mt][2 * ksp + 1]};
#pragma unroll
                for (int g = 0; g < 4; ++g) {
                    mma16816(oc[mt][2 * g],     aH, bH[g][0], bH[g][2]);
                    mma16816(oc[mt][2 * g + 1], aH, bH[g][1], bH[g][3]);
                    mma16816(oc[mt][2 * g],     aH, bL[g][0], bL[g][2]);
                    mma16816(oc[mt][2 * g + 1], aH, bL[g][1], bL[g][3]);
                    mma16816(oc[mt][2 * g],     aL, bH[g][0], bH[g][2]);
                    mma16816(oc[mt][2 * g + 1], aL, bH[g][1], bH[g][3]);
                }
            }
        }
    }
#undef KVPRE

    // ---- reduce l across the 4 lanes of each row-group ----
#pragma unroll
    for (int j = 0; j < 4; ++j) {
        l_part[j] += __shfl_xor_sync(0xFFFFFFFF, l_part[j], 1);
        l_part[j] += __shfl_xor_sync(0xFFFFFFFF, l_part[j], 2);
    }
    if ((lane & 3) == 0) {
#pragma unroll
        for (int mt = 0; mt < 2; ++mt)
#pragma unroll
            for (int half = 0; half < 2; ++half) {
                int r = wm * 32 + mt * 16 + (lane >> 2) + half * 8;
                atomicAdd((float*)(smem + FLSM + r * 4), l_part[mt * 2 + half]);
            }
    }
    __syncthreads();   // all PV done; Q area now dead -> O reduce buffer

    // wn==1 warps park their k-partial O in smem (fp32, row-major 128x64)
    if (wn == 1) {
#pragma unroll
        for (int mt = 0; mt < 2; ++mt) {
            int row = wm * 32 + mt * 16 + (lane >> 2);
#pragma unroll
            for (int nf = 0; nf < 8; ++nf) {
                int col = nf * 8 + (lane & 3) * 2;
                *(float2*)(smem + FQHI + (row * 64 + col) * 4) =
                    make_float2(oc[mt][nf][0], oc[mt][nf][1]);
                *(float2*)(smem + FQHI + ((row + 8) * 64 + col) * 4) =
                    make_float2(oc[mt][nf][2], oc[mt][nf][3]);
            }
        }
    }
    __syncthreads();

    if (wn == 0) {
#pragma unroll
        for (int mt = 0; mt < 2; ++mt)
#pragma unroll
            for (int half = 0; half < 2; ++half) {
                int r = wm * 32 + mt * 16 + (lane >> 2) + half * 8;
                float inv = 1.f / *(float*)(smem + FLSM + r * 4);
                size_t mrow = (size_t)(b * SEQ + s0 + r) * K3;
#pragma unroll
                for (int nf = 0; nf < 8; ++nf) {
                    int col = nf * 8 + (lane & 3) * 2;
                    float2 part = *(float2*)(smem + FQHI + (r * 64 + col) * 4);
                    float v0 = (oc[mt][nf][half * 2]     + part.x) * inv;
                    float v1 = (oc[mt][nf][half * 2 + 1] + part.y) * inv;
                    __nv_bfloat16 h0 = __float2bfloat16(v0);
                    __nv_bfloat16 h1 = __float2bfloat16(v1);
                    __nv_bfloat162 hp; hp.x = h0; hp.y = h1;
                    __nv_bfloat162 lp;
                    lp.x = __float2bfloat16(v0 - __bfloat162float(h0));
                    lp.y = __float2bfloat16(v1 - __bfloat162float(h1));
                    int k = h * HD + col;
                    *(__nv_bfloat162*)&g_a3[mrow + k]           = hp;
                    *(__nv_bfloat162*)&g_a3[mrow + k + EMB]     = hp;
                    *(__nv_bfloat162*)&g_a3[mrow + k + 2 * EMB] = lp;
                }
            }
    }
}

// ---------------------------------------------------------------------------
// Launch  (gemm_q is the 6th launch so ncu -s 5 -c 1 profiles it)
// ---------------------------------------------------------------------------
extern "C" void kernel_launch(void* const* d_in, const int* in_sizes, int n_in,
                              void* d_out, int out_size)
{
    const float* query = (const float*)d_in[0];
    const float* xi    = (const float*)d_in[1];
    const float* Wq    = (const float*)d_in[2];
    const float* bq    = (const float*)d_in[3];
    const float* Wk    = (const float*)d_in[4];
    const float* bk    = (const float*)d_in[5];
    const float* Wv    = (const float*)d_in[6];
    const float* bv    = (const float*)d_in[7];
    const float* Wo    = (const float*)d_in[8];
    const float* bo    = (const float*)d_in[9];
    const float* ew1   = (const float*)d_in[10];
    const float* eb1   = (const float*)d_in[11];
    const float* lng   = (const float*)d_in[12];
    const float* lnb   = (const float*)d_in[13];
    const float* ew2   = (const float*)d_in[14];
    const float* eb2   = (const float*)d_in[15];
    const float* gate  = (const float*)d_in[16];
    float* out = (float*)d_out;

    // Idempotent, capture-safe, no static guard (harness rule).
    cudaFuncSetAttribute(gemm_mma, cudaFuncAttributeMaxDynamicSharedMemorySize, GEMM_SMEM);
    cudaFuncSetAttribute(flash_tc, cudaFuncAttributeMaxDynamicSharedMemorySize, FLASH_SMEM);

    int nX = M_TOT * EMB;
    __nv_bfloat16 *x3, *a3, *w3;
    cudaGetSymbolAddress((void**)&x3, g_x3);
    cudaGetSymbolAddress((void**)&a3, g_a3);
    cudaGetSymbolAddress((void**)&w3, g_w3);

    dim3 wgrid(EMB / 32, EMB / 32), wblk(32, 8);
    dim3 ggrid(EMB / TN, M_TOT / TM);

    adapt_kernel<<<1, 32>>>(xi, ew1, eb1, lng, lnb, ew2, eb2, gate);            // 1
    split3_kernel<<<nX / 256, 256>>>(query, x3, nX);                            // 2
    wsplit3_kernel<<<wgrid, wblk>>>(Wq, w3 + (size_t)0 * EMB * K3);             // 3
    wsplit3_kernel<<<wgrid, wblk>>>(Wk, w3 + (size_t)1 * EMB * K3);             // 4
    wsplit3_kernel<<<wgrid, wblk>>>(Wv, w3 + (size_t)2 * EMB * K3);             // 5
    gemm_mma<<<ggrid, 256, GEMM_SMEM>>>(x3, w3 + (size_t)0 * EMB * K3, bq, out, 0); // 6 (profiled)
    gemm_mma<<<ggrid, 256, GEMM_SMEM>>>(x3, w3 + (size_t)1 * EMB * K3, bk, out, 1); // 7
    gemm_mma<<<ggrid, 256, GEMM_SMEM>>>(x3, w3 + (size_t)2 * EMB * K3, bv, out, 2); // 8
    wsplit3_kernel<<<wgrid, wblk>>>(Wo, w3 + (size_t)3 * EMB * K3);             // 9
    flash_tc<<<dim3(SEQ / 128, NH, BATCH), 256, FLASH_SMEM>>>();                // 10
    gemm_mma<<<ggrid, 256, GEMM_SMEM>>>(a3, w3 + (size_t)3 * EMB * K3, bo, out, 3); // 11
}

// round 10
// speedup vs baseline: 1.0200x; 1.0200x over previous
#include <cuda_runtime.h>
#include <cuda_bf16.h>
#include <cstdint>
#include <math.h>

// Problem constants
constexpr int BATCH = 2;
constexpr int SEQ   = 2048;
constexpr int EMB   = 1024;
constexpr int NH    = 16;
constexpr int HD    = 64;
constexpr int HD2   = 32;
constexpr int M_TOT = BATCH * SEQ;   // 4096

// GEMM tiling (mma.sync, 3-segment extended-K:  A3=[hi|hi|lo], B3=[hi|lo|hi])
constexpr int TM  = 128;
constexpr int TN  = 128;
constexpr int K3  = 3 * EMB;          // 3072
constexpr int KC  = 64;               // bf16 per chunk = 128 B rows
constexpr int NCH = K3 / KC;          // 48
constexpr int STAGE_BYTES = 2 * TM * 128;          // A tile + B tile = 32 KB
constexpr uint32_t GEMM_SMEM = 2 * STAGE_BYTES;    // 2-stage = 64 KB -> 2 CTAs/SM

// Flash smem layout (bytes)
constexpr uint32_t FQHI = 0;           // 16 KB (reused as O-reduce buffer at end)
constexpr uint32_t FQLO = 16384;
constexpr uint32_t FKV  = 32768;       // 2 stages x 32 KB
constexpr uint32_t FSTG = 32768;       // within stage: KHI 0, KLO 8K, VHI 16K, VLO 24K
constexpr uint32_t FLSM = 98304;       // 512 B for l
constexpr uint32_t FLASH_SMEM = 98304 + 512;

// ---------------------------------------------------------------------------
// Scratch (device globals -- no runtime allocation allowed)
// ---------------------------------------------------------------------------
__device__ float g_adapt[BATCH * EMB];

__device__ __nv_bfloat16 g_x3[(size_t)M_TOT * K3];      // [m][hi | hi | lo]
__device__ __nv_bfloat16 g_a3[(size_t)M_TOT * K3];      // attention out (written by flash)
__device__ __nv_bfloat16 g_w3[4][(size_t)EMB * K3];     // transposed [n][hi | lo | hi]

__device__ __nv_bfloat16 g_qhi[(size_t)BATCH * NH * SEQ * HD];  // [bh][s][d]
__device__ __nv_bfloat16 g_qlo[(size_t)BATCH * NH * SEQ * HD];
__device__ __nv_bfloat16 g_khi[(size_t)BATCH * NH * SEQ * HD];
__device__ __nv_bfloat16 g_klo[(size_t)BATCH * NH * SEQ * HD];
__device__ __nv_bfloat16 g_vthi[(size_t)BATCH * NH * HD * SEQ]; // [bh][d][s]
__device__ __nv_bfloat16 g_vtlo[(size_t)BATCH * NH * HD * SEQ];

// ---------------------------------------------------------------------------
// Helpers
// ---------------------------------------------------------------------------
__device__ __forceinline__ uint32_t smem_u32(const void* p) {
    uint32_t a;
    asm("{ .reg .u64 t; cvta.to.shared.u64 t, %1; cvt.u32.u64 %0, t; }" : "=r"(a) : "l"(p));
    return a;
}
#define SWZ128(off) ((off) ^ (((off) >> 3) & 0x70))

__device__ __forceinline__ void cp16(uint32_t d, const void* g) {
    asm volatile("cp.async.cg.shared.global [%0], [%1], 16;" :: "r"(d), "l"(g));
}
__device__ __forceinline__ void ldm4(uint32_t* f, uint32_t addr) {
    asm volatile("ldmatrix.sync.aligned.m8n8.x4.shared.b16 {%0,%1,%2,%3}, [%4];"
        : "=r"(f[0]), "=r"(f[1]), "=r"(f[2]), "=r"(f[3]) : "r"(addr));
}
__device__ __forceinline__ void mma16816(float* c, const uint32_t* a, uint32_t b0, uint32_t b1) {
    asm volatile("mma.sync.aligned.m16n8k16.row.col.f32.bf16.bf16.f32 "
        "{%0,%1,%2,%3}, {%4,%5,%6,%7}, {%8,%9}, {%0,%1,%2,%3};"
        : "+f"(c[0]), "+f"(c[1]), "+f"(c[2]), "+f"(c[3])
        : "r"(a[0]), "r"(a[1]), "r"(a[2]), "r"(a[3]), "r"(b0), "r"(b1));
}
__device__ __forceinline__ float fast_ex2(float x) {
    float y; asm("ex2.approx.f32 %0, %1;" : "=f"(y) : "f"(x)); return y;
}
__device__ __forceinline__ uint32_t pack_bf16x2(__nv_bfloat16 lo, __nv_bfloat16 hi) {
    __nv_bfloat162 t; t.x = lo; t.y = hi;
    uint32_t r;
    memcpy(&r, &t, 4);
    return r;
}

// ---------------------------------------------------------------------------
// Kernel: adapt
// ---------------------------------------------------------------------------
__global__ void adapt_kernel(const float* __restrict__ xi,
                             const float* __restrict__ ew1, const float* __restrict__ eb1,
                             const float* __restrict__ lng, const float* __restrict__ lnb,
                             const float* __restrict__ ew2, const float* __restrict__ eb2,
                             const float* __restrict__ gate)
{
    int b = threadIdx.x;
    if (b >= BATCH) return;
    float x[HD2];
    float xv = xi[b];
    float mu = 0.f;
#pragma unroll
    for (int i = 0; i < HD2; ++i) { x[i] = xv * ew1[i] + eb1[i]; mu += x[i]; }
    mu *= (1.0f / HD2);
    float var = 0.f;
#pragma unroll
    for (int i = 0; i < HD2; ++i) { float d = x[i] - mu; var += d * d; }
    var *= (1.0f / HD2);
    float rs = rsqrtf(var + 1e-5f);
#pragma unroll
    for (int i = 0; i < HD2; ++i) {
        float xn = (x[i] - mu) * rs * lng[i] + lnb[i];
        x[i] = 0.5f * xn * (1.f + erff(xn * 0.70710678118654752f));
    }
    float sg[NH];
#pragma unroll
    for (int h = 0; h < NH; ++h) sg[h] = 1.f / (1.f + expf(-gate[h]));
    for (int d = 0; d < HD; ++d) {
        float xe = eb2[d];
#pragma unroll
        for (int i = 0; i < HD2; ++i) xe += x[i] * ew2[i * HD + d];
#pragma unroll
        for (int h = 0; h < NH; ++h)
            g_adapt[b * EMB + h * HD + d] = 1.f + sg[h] * xe;
    }
}

// ---------------------------------------------------------------------------
// Kernel: fp32 [M,1024] -> bf16 [M, 3072] = [hi | hi | lo]
// ---------------------------------------------------------------------------
__global__ void __launch_bounds__(256)
split3_kernel(const float* __restrict__ in, __nv_bfloat16* __restrict__ out3, int n)
{
    int i = blockIdx.x * 256 + threadIdx.x;
    if (i < n) {
        int m = i >> 10, k = i & 1023;
        float x = in[i];
        __nv_bfloat16 h = __float2bfloat16(x);
        __nv_bfloat16 l = __float2bfloat16(x - __bfloat162float(h));
        size_t base = (size_t)m * K3 + k;
        out3[base]           = h;
        out3[base + EMB]     = h;
        out3[base + 2 * EMB] = l;
    }
}

// ---------------------------------------------------------------------------
// Kernel: W[K,N] fp32 -> transposed bf16 [N, 3072] = [hi | lo | hi]
// ---------------------------------------------------------------------------
__global__ void __launch_bounds__(256)
wsplit3_kernel(const float* __restrict__ W, __nv_bfloat16* __restrict__ out3)
{
    __shared__ float t[32][33];
    int n0 = blockIdx.x * 32, k0 = blockIdx.y * 32;
    int tx = threadIdx.x, ty = threadIdx.y;   // (32, 8)
#pragma unroll
    for (int i = 0; i < 32; i += 8)
        t[ty + i][tx] = W[(size_t)(k0 + ty + i) * EMB + n0 + tx];
    __syncthreads();
#pragma unroll
    for (int i = 0; i < 32; i += 8) {
        float x = t[tx][ty + i];              // k=k0+tx, n=n0+ty+i
        __nv_bfloat16 h = __float2bfloat16(x);
        __nv_bfloat16 l = __float2bfloat16(x - __bfloat162float(h));
        size_t base = (size_t)(n0 + ty + i) * K3 + k0 + tx;
        out3[base]           = h;
        out3[base + EMB]     = l;
        out3[base + 2 * EMB] = h;
    }
}

// ---------------------------------------------------------------------------
// Kernel: mma.sync bf16 GEMM  C[M,N] = A3[M,K3] * B3[N,K3]^T + bias, fused epi.
// 128 threads, 4 warps in a 2x2 grid, 64x64 warp tiles -> 1.5x less smem
// fragment traffic and 2 CTAs/SM. Modes as before.
// ---------------------------------------------------------------------------
__global__ void __launch_bounds__(128)
gemm_mma(const __nv_bfloat16* __restrict__ A3, const __nv_bfloat16* __restrict__ B3,
         const float* __restrict__ bias, float* __restrict__ out, int mode)
{
    extern __shared__ __align__(1024) char smem[];
    const uint32_t sb = smem_u32(smem);
    const int tid  = threadIdx.x;
    const int lane = tid & 31;
    const int wid  = tid >> 5;        // 0..3
    const int wm   = wid >> 1;        // 0..1
    const int wn   = wid & 1;         // 0..1
    const int m0 = blockIdx.y * TM;
    const int n0 = blockIdx.x * TN;

    const __nv_bfloat16* Ab = A3 + (size_t)m0 * K3;
    const __nv_bfloat16* Bb = B3 + (size_t)n0 * K3;

    float c[4][8][4];
#pragma unroll
    for (int a = 0; a < 4; ++a)
#pragma unroll
        for (int b = 0; b < 8; ++b)
#pragma unroll
            for (int d = 0; d < 4; ++d) c[a][b][d] = 0.f;

#define PREFETCH(kc)                                                                   \
    do {                                                                               \
        uint32_t st = sb + ((kc) & 1) * STAGE_BYTES;                                   \
        _Pragma("unroll")                                                              \
        for (int i = 0; i < 8; ++i) {                                                  \
            int idx = tid + i * 128;                                                   \
            int r = idx >> 3, u = idx & 7;                                             \
            cp16(st + SWZ128(r * 128 + u * 16), Ab + (size_t)r * K3 + (kc) * KC + u * 8); \
            cp16(st + TM * 128 + SWZ128(r * 128 + u * 16),                             \
                 Bb + (size_t)r * K3 + (kc) * KC + u * 8);                             \
        }                                                                              \
        asm volatile("cp.async.commit_group;");                                        \
    } while (0)

    PREFETCH(0);

    for (int kc = 0; kc < NCH; ++kc) {
        if (kc + 1 < NCH) {
            PREFETCH(kc + 1);
            asm volatile("cp.async.wait_group 1;");
        } else {
            asm volatile("cp.async.wait_group 0;");
        }
        __syncthreads();

        const uint32_t sA = sb + (kc & 1) * STAGE_BYTES;
        const uint32_t sB = sA + TM * 128;
        const int rr = lane & 15;

#pragma unroll
        for (int ks = 0; ks < 4; ++ks) {
            const int uu = 2 * ks + (lane >> 4);
            uint32_t afr[4][4], bfr[4][4];
#pragma unroll
            for (int mt = 0; mt < 4; ++mt)
                ldm4(afr[mt], sA + SWZ128((wm * 64 + mt * 16 + rr) * 128 + uu * 16));
#pragma unroll
            for (int ng = 0; ng < 4; ++ng)
                ldm4(bfr[ng], sB + SWZ128((wn * 64 + ng * 16 + rr) * 128 + uu * 16));
#pragma unroll
            for (int mt = 0; mt < 4; ++mt)
#pragma unroll
                for (int ng = 0; ng < 4; ++ng) {
                    mma16816(c[mt][ng * 2],     afr[mt], bfr[ng][0], bfr[ng][2]);
                    mma16816(c[mt][ng * 2 + 1], afr[mt], bfr[ng][1], bfr[ng][3]);
                }
        }
        __syncthreads();
    }
#undef PREFETCH

    // ---------------- epilogues ----------------
    if (mode == 2) {
        // V: stage transposed bf16 hi/lo in smem, then coalesced store to [bh][d][s]
#pragma unroll
        for (int mt = 0; mt < 4; ++mt) {
            int mrow = wm * 64 + mt * 16 + (lane >> 2);
#pragma unroll
            for (int nt = 0; nt < 8; ++nt) {
                int nl = wn * 64 + nt * 8 + (lane & 3) * 2;
                float b0 = bias[n0 + nl], b1 = bias[n0 + nl + 1];
#pragma unroll
                for (int half = 0; half < 2; ++half) {
                    int ml = mrow + half * 8;
                    float v0 = c[mt][nt][half * 2] + b0;
                    float v1 = c[mt][nt][half * 2 + 1] + b1;
                    __nv_bfloat16 h0 = __float2bfloat16(v0);
                    __nv_bfloat16 h1 = __float2bfloat16(v1);
                    __nv_bfloat16 l0 = __float2bfloat16(v0 - __bfloat162float(h0));
                    __nv_bfloat16 l1 = __float2bfloat16(v1 - __bfloat162float(h1));
                    *(__nv_bfloat16*)(smem + nl * 256 + ml * 2) = h0;
                    *(__nv_bfloat16*)(smem + (nl + 1) * 256 + ml * 2) = h1;
                    *(__nv_bfloat16*)(smem + 32768 + nl * 256 + ml * 2) = l0;
                    *(__nv_bfloat16*)(smem + 32768 + (nl + 1) * 256 + ml * 2) = l1;
                }
            }
        }
        __syncthreads();
        int bq = m0 >> 11, sq = m0 & 2047;
        int hbase = n0 >> 6;
        for (int cidx = tid; cidx < 2048; cidx += 128) {
            int nn = cidx >> 4, mc = cidx & 15;
            uint4 hv = *(uint4*)(smem + nn * 256 + mc * 16);
            uint4 lv = *(uint4*)(smem + 32768 + nn * 256 + mc * 16);
            size_t o = (((size_t)(bq * NH + hbase + (nn >> 6)) * HD + (nn & 63)) * SEQ
                        + sq + mc * 8);
            *(uint4*)&g_vthi[o] = hv;
            *(uint4*)&g_vtlo[o] = lv;
        }
        return;
    }

#pragma unroll
    for (int mt = 0; mt < 4; ++mt) {
        int row0 = wm * 64 + mt * 16 + (lane >> 2);
#pragma unroll
        for (int nt = 0; nt < 8; ++nt) {
            int n = n0 + wn * 64 + nt * 8 + (lane & 3) * 2;
            float b0 = bias[n], b1 = bias[n + 1];
#pragma unroll
            for (int half = 0; half < 2; ++half) {
                int m = m0 + row0 + half * 8;
                int b = m >> 11, s = m & 2047;
                float v0 = c[mt][nt][half * 2] + b0;
                float v1 = c[mt][nt][half * 2 + 1] + b1;
                if (mode == 3) {
                    *(float2*)&out[(size_t)m * EMB + n] = make_float2(v0, v1);
                } else {
                    // Q: fold 1/8 * log2(e); K: adapt only
                    const float sc0 = (mode == 0) ? 0.18033688f : 1.0f;  // 1.442695/8
                    v0 *= g_adapt[b * EMB + n] * sc0;
                    v1 *= g_adapt[b * EMB + n + 1] * sc0;
                    __nv_bfloat16 h0 = __float2bfloat16(v0);
                    __nv_bfloat16 h1 = __float2bfloat16(v1);
                    __nv_bfloat16 l0 = __float2bfloat16(v0 - __bfloat162float(h0));
                    __nv_bfloat16 l1 = __float2bfloat16(v1 - __bfloat162float(h1));
                    int h = n >> 6, d = n & 63;
                    size_t o = ((size_t)(b * NH + h) * SEQ + s) * HD + d;
                    __nv_bfloat162 hp; hp.x = h0; hp.y = h1;
                    __nv_bfloat162 lp; lp.x = l0; lp.y = l1;
                    if (mode == 0) {
                        *(__nv_bfloat162*)&g_qhi[o] = hp;
                        *(__nv_bfloat162*)&g_qlo[o] = lp;
                    } else {
                        *(__nv_bfloat162*)&g_khi[o] = hp;
                        *(__nv_bfloat162*)&g_klo[o] = lp;
                    }
                }
            }
        }
    }
}

// ---------------------------------------------------------------------------
// Kernel: tensor-core flash attention, P kept in registers (fragment reuse).
// (unchanged from R8, the 733us best)
// ---------------------------------------------------------------------------
__global__ void __launch_bounds__(256)
flash_tc()
{
    extern __shared__ __align__(1024) char smem[];
    const uint32_t sb = smem_u32(smem);
    const int tid = threadIdx.x, lane = tid & 31, wid = tid >> 5;
    const int wm = wid >> 1, wn = wid & 1;
    const int s0 = blockIdx.x * 128;
    const int h  = blockIdx.y, b = blockIdx.z;
    const int bh = b * NH + h;
    const int rr = lane & 15;

    if (tid < 128) *(float*)(smem + FLSM + tid * 4) = 0.f;

    const __nv_bfloat16* qhi = g_qhi + ((size_t)bh * SEQ + s0) * HD;
    const __nv_bfloat16* qlo = g_qlo + ((size_t)bh * SEQ + s0) * HD;
    const __nv_bfloat16* khi = g_khi + (size_t)bh * SEQ * HD;
    const __nv_bfloat16* klo = g_klo + (size_t)bh * SEQ * HD;
    const __nv_bfloat16* vth = g_vthi + (size_t)bh * HD * SEQ;
    const __nv_bfloat16* vtl = g_vtlo + (size_t)bh * HD * SEQ;

    // Q tiles (once)
#pragma unroll
    for (int i = 0; i < 4; ++i) {
        int idx = tid + i * 256;       // 0..1023
        int r = idx >> 3, u = idx & 7;
        cp16(sb + FQHI + SWZ128(r * 128 + u * 16), qhi + r * HD + u * 8);
        cp16(sb + FQLO + SWZ128(r * 128 + u * 16), qlo + r * HD + u * 8);
    }
    asm volatile("cp.async.commit_group;");

#define KVPRE(kb)                                                                       \
    do {                                                                                \
        uint32_t st = sb + FKV + ((kb) & 1) * FSTG;                                     \
        _Pragma("unroll")                                                               \
        for (int i = 0; i < 2; ++i) {                                                   \
            int idx = tid + i * 256;     /* 0..511 */                                   \
            int r = idx >> 3, u = idx & 7;                                              \
            uint32_t sw = SWZ128(r * 128 + u * 16);                                     \
            cp16(st + sw,          khi + ((size_t)(kb) * 64 + r) * HD + u * 8);         \
            cp16(st + 8192 + sw,   klo + ((size_t)(kb) * 64 + r) * HD + u * 8);         \
            cp16(st + 16384 + sw,  vth + (size_t)r * SEQ + (kb) * 64 + u * 8);          \
            cp16(st + 24576 + sw,  vtl + (size_t)r * SEQ + (kb) * 64 + u * 8);          \
        }                                                                               \
        asm volatile("cp.async.commit_group;");                                         \
    } while (0)

    KVPRE(0);

    float oc[2][8][4];
#pragma unroll
    for (int a = 0; a < 2; ++a)
#pragma unroll
        for (int f = 0; f < 8; ++f)
#pragma unroll
            for (int d = 0; d < 4; ++d) oc[a][f][d] = 0.f;
    float l_part[4] = {0.f, 0.f, 0.f, 0.f};

#pragma unroll 1
    for (int kb = 0; kb < SEQ / 64; ++kb) {
        asm volatile("cp.async.wait_group 0;");
        __syncthreads();
        if (kb + 1 < SEQ / 64) KVPRE(kb + 1);

        const uint32_t stg = sb + FKV + (kb & 1) * FSTG;

        // ---- S = Q K^T (3-term) ----
        float sc[2][4][4];
#pragma unroll
        for (int a = 0; a < 2; ++a)
#pragma unroll
            for (int f = 0; f < 4; ++f)
#pragma unroll
                for (int d = 0; d < 4; ++d) sc[a][f][d] = 0.f;

#pragma unroll
        for (int ks = 0; ks < 4; ++ks) {
            const int uu = 2 * ks + (lane >> 4);
            uint32_t aH[2][4], aL[2][4], bH[2][4], bL[2][4];
#pragma unroll
            for (int mt = 0; mt < 2; ++mt) {
                uint32_t sw = SWZ128((wm * 32 + mt * 16 + rr) * 128 + uu * 16);
                ldm4(aH[mt], sb + FQHI + sw);
                ldm4(aL[mt], sb + FQLO + sw);
            }
#pragma unroll
            for (int ng = 0; ng < 2; ++ng) {
                uint32_t sw = SWZ128((wn * 32 + ng * 16 + rr) * 128 + uu * 16);
                ldm4(bH[ng], stg + sw);
                ldm4(bL[ng], stg + 8192 + sw);
            }
#pragma unroll
            for (int mt = 0; mt < 2; ++mt)
#pragma unroll
                for (int ng = 0; ng < 2; ++ng) {
                    mma16816(sc[mt][ng * 2],     aH[mt], bH[ng][0], bH[ng][2]);
                    mma16816(sc[mt][ng * 2 + 1], aH[mt], bH[ng][1], bH[ng][3]);
                    mma16816(sc[mt][ng * 2],     aH[mt], bL[ng][0], bL[ng][2]);
                    mma16816(sc[mt][ng * 2 + 1], aH[mt], bL[ng][1], bL[ng][3]);
                    mma16816(sc[mt][ng * 2],     aL[mt], bH[ng][0], bH[ng][2]);
                    mma16816(sc[mt][ng * 2 + 1], aL[mt], bH[ng][1], bH[ng][3]);
                }
        }

        // ---- p = 2^s; pack bf16 hi/lo A-fragments directly in registers ----
        uint32_t pAh[2][4], pBh[2][4], pAl[2][4], pBl[2][4];
#pragma unroll
        for (int mt = 0; mt < 2; ++mt)
#pragma unroll
            for (int nf = 0; nf < 4; ++nf) {
                float p0 = fast_ex2(sc[mt][nf][0]);
                float p1 = fast_ex2(sc[mt][nf][1]);
                float p2 = fast_ex2(sc[mt][nf][2]);
                float p3 = fast_ex2(sc[mt][nf][3]);
                l_part[mt * 2 + 0] += p0 + p1;
                l_part[mt * 2 + 1] += p2 + p3;
                __nv_bfloat16 h0 = __float2bfloat16(p0);
                __nv_bfloat16 h1 = __float2bfloat16(p1);
                __nv_bfloat16 h2 = __float2bfloat16(p2);
                __nv_bfloat16 h3 = __float2bfloat16(p3);
                pAh[mt][nf] = pack_bf16x2(h0, h1);
                pBh[mt][nf] = pack_bf16x2(h2, h3);
                pAl[mt][nf] = pack_bf16x2(
                    __float2bfloat16(p0 - __bfloat162float(h0)),
                    __float2bfloat16(p1 - __bfloat162float(h1)));
                pBl[mt][nf] = pack_bf16x2(
                    __float2bfloat16(p2 - __bfloat162float(h2)),
                    __float2bfloat16(p3 - __bfloat162float(h3)));
            }

        // ---- O_partial += P V over this warp's 32 keys, all 64 d ----
#pragma unroll
        for (int ksp = 0; ksp < 2; ++ksp) {
            const int uu = 2 * (wn * 2 + ksp) + (lane >> 4);
            uint32_t bH[4][4], bL[4][4];
#pragma unroll
            for (int g = 0; g < 4; ++g) {
                uint32_t sw = SWZ128((g * 16 + rr) * 128 + uu * 16);
                ldm4(bH[g], stg + 16384 + sw);
                ldm4(bL[g], stg + 24576 + sw);
            }
#pragma unroll
            for (int mt = 0; mt < 2; ++mt) {
                uint32_t aH[4] = {pAh[mt][2 * ksp], pBh[mt][2 * ksp],
                                  pAh[mt][2 * ksp + 1], pBh[mt][2 * ksp + 1]};
                uint32_t aL[4] = {pAl[mt][2 * ksp], pBl[mt][2 * ksp],
                                  pAl[mt][2 * ksp + 1], pBl[mt][2 * ksp + 1]};
#pragma unroll
                for (int g = 0; g < 4; ++g) {
                    mma16816(oc[mt][2 * g],     aH, bH[g][0], bH[g][2]);
                    mma16816(oc[mt][2 * g + 1], aH, bH[g][1], bH[g][3]);
                    mma16816(oc[mt][2 * g],     aH, bL[g][0], bL[g][2]);
                    mma16816(oc[mt][2 * g + 1], aH, bL[g][1], bL[g][3]);
                    mma16816(oc[mt][2 * g],     aL, bH[g][0], bH[g][2]);
                    mma16816(oc[mt][2 * g + 1], aL, bH[g][1], bH[g][3]);
                }
            }
        }
    }
#undef KVPRE

    // ---- reduce l across the 4 lanes of each row-group ----
#pragma unroll
    for (int j = 0; j < 4; ++j) {
        l_part[j] += __shfl_xor_sync(0xFFFFFFFF, l_part[j], 1);
        l_part[j] += __shfl_xor_sync(0xFFFFFFFF, l_part[j], 2);
    }
    if ((lane & 3) == 0) {
#pragma unroll
        for (int mt = 0; mt < 2; ++mt)
#pragma unroll
            for (int half = 0; half < 2; ++half) {
                int r = wm * 32 + mt * 16 + (lane >> 2) + half * 8;
                atomicAdd((float*)(smem + FLSM + r * 4), l_part[mt * 2 + half]);
            }
    }
    __syncthreads();   // all PV done; Q area now dead -> O reduce buffer

    // wn==1 warps park their k-partial O in smem (fp32, row-major 128x64)
    if (wn == 1) {
#pragma unroll
        for (int mt = 0; mt < 2; ++mt) {
            int row = wm * 32 + mt * 16 + (lane >> 2);
#pragma unroll
            for (int nf = 0; nf < 8; ++nf) {
                int col = nf * 8 + (lane & 3) * 2;
                *(float2*)(smem + FQHI + (row * 64 + col) * 4) =
                    make_float2(oc[mt][nf][0], oc[mt][nf][1]);
                *(float2*)(smem + FQHI + ((row + 8) * 64 + col) * 4) =
                    make_float2(oc[mt][nf][2], oc[mt][nf][3]);
            }
        }
    }
    __syncthreads();

    if (wn == 0) {
#pragma unroll
        for (int mt = 0; mt < 2; ++mt)
#pragma unroll
            for (int half = 0; half < 2; ++half) {
                int r = wm * 32 + mt * 16 + (lane >> 2) + half * 8;
                float inv = 1.f / *(float*)(smem + FLSM + r * 4);
                size_t mrow = (size_t)(b * SEQ + s0 + r) * K3;
#pragma unroll
                for (int nf = 0; nf < 8; ++nf) {
                    int col = nf * 8 + (lane & 3) * 2;
                    float2 part = *(float2*)(smem + FQHI + (r * 64 + col) * 4);
                    float v0 = (oc[mt][nf][half * 2]     + part.x) * inv;
                    float v1 = (oc[mt][nf][half * 2 + 1] + part.y) * inv;
                    __nv_bfloat16 h0 = __float2bfloat16(v0);
                    __nv_bfloat16 h1 = __float2bfloat16(v1);
                    __nv_bfloat162 hp; hp.x = h0; hp.y = h1;
                    __nv_bfloat162 lp;
                    lp.x = __float2bfloat16(v0 - __bfloat162float(h0));
                    lp.y = __float2bfloat16(v1 - __bfloat162float(h1));
                    int k = h * HD + col;
                    *(__nv_bfloat162*)&g_a3[mrow + k]           = hp;
                    *(__nv_bfloat162*)&g_a3[mrow + k + EMB]     = hp;
                    *(__nv_bfloat162*)&g_a3[mrow + k + 2 * EMB] = lp;
                }
            }
    }
}

// ---------------------------------------------------------------------------
// Launch
// ---------------------------------------------------------------------------
extern "C" void kernel_launch(void* const* d_in, const int* in_sizes, int n_in,
                              void* d_out, int out_size)
{
    const float* query = (const float*)d_in[0];
    const float* xi    = (const float*)d_in[1];
    const float* Wq    = (const float*)d_in[2];
    const float* bq    = (const float*)d_in[3];
    const float* Wk    = (const float*)d_in[4];
    const float* bk    = (const float*)d_in[5];
    const float* Wv    = (const float*)d_in[6];
    const float* bv    = (const float*)d_in[7];
    const float* Wo    = (const float*)d_in[8];
    const float* bo    = (const float*)d_in[9];
    const float* ew1   = (const float*)d_in[10];
    const float* eb1   = (const float*)d_in[11];
    const float* lng   = (const float*)d_in[12];
    const float* lnb   = (const float*)d_in[13];
    const float* ew2   = (const float*)d_in[14];
    const float* eb2   = (const float*)d_in[15];
    const float* gate  = (const float*)d_in[16];
    float* out = (float*)d_out;

    // Idempotent, capture-safe, no static guard (harness rule).
    cudaFuncSetAttribute(gemm_mma, cudaFuncAttributeMaxDynamicSharedMemorySize, GEMM_SMEM);
    cudaFuncSetAttribute(flash_tc, cudaFuncAttributeMaxDynamicSharedMemorySize, FLASH_SMEM);

    int nX = M_TOT * EMB;
    __nv_bfloat16 *x3, *a3, *w3;
    cudaGetSymbolAddress((void**)&x3, g_x3);
    cudaGetSymbolAddress((void**)&a3, g_a3);
    cudaGetSymbolAddress((void**)&w3, g_w3);

    dim3 wgrid(EMB / 32, EMB / 32), wblk(32, 8);
    dim3 ggrid(EMB / TN, M_TOT / TM);

    adapt_kernel<<<1, 32>>>(xi, ew1, eb1, lng, lnb, ew2, eb2, gate);
    split3_kernel<<<nX / 256, 256>>>(query, x3, nX);
    wsplit3_kernel<<<wgrid, wblk>>>(Wq, w3 + (size_t)0 * EMB * K3);
    wsplit3_kernel<<<wgrid, wblk>>>(Wk, w3 + (size_t)1 * EMB * K3);
    wsplit3_kernel<<<wgrid, wblk>>>(Wv, w3 + (size_t)2 * EMB * K3);
    gemm_mma<<<ggrid, 128, GEMM_SMEM>>>(x3, w3 + (size_t)0 * EMB * K3, bq, out, 0);
    gemm_mma<<<ggrid, 128, GEMM_SMEM>>>(x3, w3 + (size_t)1 * EMB * K3, bk, out, 1);
    gemm_mma<<<ggrid, 128, GEMM_SMEM>>>(x3, w3 + (size_t)2 * EMB * K3, bv, out, 2);
    wsplit3_kernel<<<wgrid, wblk>>>(Wo, w3 + (size_t)3 * EMB * K3);
    flash_tc<<<dim3(SEQ / 128, NH, BATCH), 256, FLASH_SMEM>>>();
    gemm_mma<<<ggrid, 128, GEMM_SMEM>>>(a3, w3 + (size_t)3 * EMB * K3, bo, out, 3);
}

// round 11
// speedup vs baseline: 1.8409x; 1.8049x over previous
#include <cuda_runtime.h>
#include <cuda_fp16.h>
#include <cstdint>
#include <math.h>

// Problem constants
constexpr int BATCH = 2;
constexpr int SEQ   = 2048;
constexpr int EMB   = 1024;
constexpr int NH    = 16;
constexpr int HD    = 64;
constexpr int HD2   = 32;
constexpr int M_TOT = BATCH * SEQ;   // 4096

// GEMM tiling (mma.sync fp16; A = x (K=1024, reused for both halves),
// B = [Whi | Wlo] (K2=2048))
constexpr int TM  = 128;
constexpr int TN  = 128;
constexpr int K2  = 2 * EMB;          // 2048
constexpr int KC  = 64;               // fp16 per chunk = 128 B rows
constexpr int NCH = K2 / KC;          // 32
constexpr int STAGE_BYTES = 2 * TM * 128;          // A tile + B tile = 32 KB
constexpr uint32_t GEMM_SMEM = 2 * STAGE_BYTES;    // 64 KB

// Flash smem layout (bytes)
constexpr uint32_t FQ   = 0;           // 16 KB q fp16 (reused for O-reduce)
constexpr uint32_t FKV  = 16384;       // 2 stages x 16 KB (K 8K, V 8K)
constexpr uint32_t FSTG = 16384;
constexpr uint32_t FLSM = 49152;       // 512 B for l
constexpr uint32_t FLASH_SMEM = 49152 + 512;

// ---------------------------------------------------------------------------
// Scratch (device globals -- no runtime allocation allowed)
// ---------------------------------------------------------------------------
__device__ float g_adapt[BATCH * EMB];

__device__ __half g_xh[(size_t)M_TOT * EMB];        // x rounded to fp16
__device__ __half g_ah[(size_t)M_TOT * EMB];        // attention out fp16
__device__ __half g_w2[4][(size_t)EMB * K2];        // transposed [n][whi | wlo]

__device__ __half g_qh[(size_t)BATCH * NH * SEQ * HD];  // [bh][s][d]
__device__ __half g_kh[(size_t)BATCH * NH * SEQ * HD];
__device__ __half g_vth[(size_t)BATCH * NH * HD * SEQ]; // [bh][d][s]

// ---------------------------------------------------------------------------
// Helpers
// ---------------------------------------------------------------------------
__device__ __forceinline__ uint32_t smem_u32(const void* p) {
    uint32_t a;
    asm("{ .reg .u64 t; cvta.to.shared.u64 t, %1; cvt.u32.u64 %0, t; }" : "=r"(a) : "l"(p));
    return a;
}
#define SWZ128(off) ((off) ^ (((off) >> 3) & 0x70))

__device__ __forceinline__ void cp16(uint32_t d, const void* g) {
    asm volatile("cp.async.cg.shared.global [%0], [%1], 16;" :: "r"(d), "l"(g));
}
__device__ __forceinline__ void ldm4(uint32_t* f, uint32_t addr) {
    asm volatile("ldmatrix.sync.aligned.m8n8.x4.shared.b16 {%0,%1,%2,%3}, [%4];"
        : "=r"(f[0]), "=r"(f[1]), "=r"(f[2]), "=r"(f[3]) : "r"(addr));
}
__device__ __forceinline__ void mma16816(float* c, const uint32_t* a, uint32_t b0, uint32_t b1) {
    asm volatile("mma.sync.aligned.m16n8k16.row.col.f32.f16.f16.f32 "
        "{%0,%1,%2,%3}, {%4,%5,%6,%7}, {%8,%9}, {%0,%1,%2,%3};"
        : "+f"(c[0]), "+f"(c[1]), "+f"(c[2]), "+f"(c[3])
        : "r"(a[0]), "r"(a[1]), "r"(a[2]), "r"(a[3]), "r"(b0), "r"(b1));
}
__device__ __forceinline__ float fast_ex2(float x) {
    float y; asm("ex2.approx.f32 %0, %1;" : "=f"(y) : "f"(x)); return y;
}
__device__ __forceinline__ uint32_t pack_h2(float a, float b) {
    __half2 t = __floats2half2_rn(a, b);
    uint32_t r;
    memcpy(&r, &t, 4);
    return r;
}

// ---------------------------------------------------------------------------
// Kernel: adapt
// ---------------------------------------------------------------------------
__global__ void adapt_kernel(const float* __restrict__ xi,
                             const float* __restrict__ ew1, const float* __restrict__ eb1,
                             const float* __restrict__ lng, const float* __restrict__ lnb,
                             const float* __restrict__ ew2, const float* __restrict__ eb2,
                             const float* __restrict__ gate)
{
    int b = threadIdx.x;
    if (b >= BATCH) return;
    float x[HD2];
    float xv = xi[b];
    float mu = 0.f;
#pragma unroll
    for (int i = 0; i < HD2; ++i) { x[i] = xv * ew1[i] + eb1[i]; mu += x[i]; }
    mu *= (1.0f / HD2);
    float var = 0.f;
#pragma unroll
    for (int i = 0; i < HD2; ++i) { float d = x[i] - mu; var += d * d; }
    var *= (1.0f / HD2);
    float rs = rsqrtf(var + 1e-5f);
#pragma unroll
    for (int i = 0; i < HD2; ++i) {
        float xn = (x[i] - mu) * rs * lng[i] + lnb[i];
        x[i] = 0.5f * xn * (1.f + erff(xn * 0.70710678118654752f));
    }
    float sg[NH];
#pragma unroll
    for (int h = 0; h < NH; ++h) sg[h] = 1.f / (1.f + expf(-gate[h]));
    for (int d = 0; d < HD; ++d) {
        float xe = eb2[d];
#pragma unroll
        for (int i = 0; i < HD2; ++i) xe += x[i] * ew2[i * HD + d];
#pragma unroll
        for (int h = 0; h < NH; ++h)
            g_adapt[b * EMB + h * HD + d] = 1.f + sg[h] * xe;
    }
}

// ---------------------------------------------------------------------------
// Kernel: fp32 -> fp16 (plain)
// ---------------------------------------------------------------------------
__global__ void __launch_bounds__(256)
half_kernel(const float* __restrict__ in, __half* __restrict__ out, int n)
{
    int i = blockIdx.x * 256 + threadIdx.x;
    if (i < n) out[i] = __float2half_rn(in[i]);
}

// ---------------------------------------------------------------------------
// Kernel: W[K,N] fp32 -> transposed fp16 [N, 2048] = [hi | lo]
// ---------------------------------------------------------------------------
__global__ void __launch_bounds__(256)
wsplit2_kernel(const float* __restrict__ W, __half* __restrict__ out2)
{
    __shared__ float t[32][33];
    int n0 = blockIdx.x * 32, k0 = blockIdx.y * 32;
    int tx = threadIdx.x, ty = threadIdx.y;   // (32, 8)
#pragma unroll
    for (int i = 0; i < 32; i += 8)
        t[ty + i][tx] = W[(size_t)(k0 + ty + i) * EMB + n0 + tx];
    __syncthreads();
#pragma unroll
    for (int i = 0; i < 32; i += 8) {
        float x = t[tx][ty + i];              // k=k0+tx, n=n0+ty+i
        __half h = __float2half_rn(x);
        __half l = __float2half_rn(x - __half2float(h));
        size_t base = (size_t)(n0 + ty + i) * K2 + k0 + tx;
        out2[base]       = h;
        out2[base + EMB] = l;
    }
}

// ---------------------------------------------------------------------------
// Kernel: mma.sync fp16 GEMM  C[M,N] = A[M,1024] * ([Whi|Wlo])[N,2048]^T + bias
// A is read twice (chunks 0..15 and 16..31 both map to x's K range).
// mode 0: Q -> *adapt*(log2e/8) -> g_qh   1: K -> *adapt -> g_kh
// mode 2: V -> transpose -> g_vth          3: O -> out fp32
// ---------------------------------------------------------------------------
__global__ void __launch_bounds__(256)
gemm_mma(const __half* __restrict__ Ah, const __half* __restrict__ B2,
         const float* __restrict__ bias, float* __restrict__ out, int mode)
{
    extern __shared__ __align__(1024) char smem[];
    const uint32_t sb = smem_u32(smem);
    const int tid  = threadIdx.x;
    const int lane = tid & 31;
    const int wid  = tid >> 5;
    const int wm   = wid >> 1;        // 0..3
    const int wn   = wid & 1;         // 0..1
    const int m0 = blockIdx.y * TM;
    const int n0 = blockIdx.x * TN;

    const __half* Ab = Ah + (size_t)m0 * EMB;
    const __half* Bb = B2 + (size_t)n0 * K2;

    float c[2][8][4];
#pragma unroll
    for (int a = 0; a < 2; ++a)
#pragma unroll
        for (int b = 0; b < 8; ++b)
#pragma unroll
            for (int d = 0; d < 4; ++d) c[a][b][d] = 0.f;

#define PREFETCH(kc)                                                                   \
    do {                                                                               \
        uint32_t st = sb + ((kc) & 1) * STAGE_BYTES;                                   \
        int ka = ((kc) & 15) * KC;                                                     \
        _Pragma("unroll")                                                              \
        for (int i = 0; i < 4; ++i) {                                                  \
            int idx = tid + i * 256;                                                   \
            int r = idx >> 3, u = idx & 7;                                             \
            cp16(st + SWZ128(r * 128 + u * 16), Ab + (size_t)r * EMB + ka + u * 8);    \
            cp16(st + TM * 128 + SWZ128(r * 128 + u * 16),                             \
                 Bb + (size_t)r * K2 + (kc) * KC + u * 8);                             \
        }                                                                              \
        asm volatile("cp.async.commit_group;");                                        \
    } while (0)

    PREFETCH(0);

    for (int kc = 0; kc < NCH; ++kc) {
        if (kc + 1 < NCH) {
            PREFETCH(kc + 1);
            asm volatile("cp.async.wait_group 1;");
        } else {
            asm volatile("cp.async.wait_group 0;");
        }
        __syncthreads();

        const uint32_t sA = sb + (kc & 1) * STAGE_BYTES;
        const uint32_t sB = sA + TM * 128;
        const int rr = lane & 15;

#pragma unroll
        for (int ks = 0; ks < 4; ++ks) {
            const int uu = 2 * ks + (lane >> 4);
            uint32_t afr[2][4], bfr[4][4];
#pragma unroll
            for (int mt = 0; mt < 2; ++mt)
                ldm4(afr[mt], sA + SWZ128((wm * 32 + mt * 16 + rr) * 128 + uu * 16));
#pragma unroll
            for (int ng = 0; ng < 4; ++ng)
                ldm4(bfr[ng], sB + SWZ128((wn * 64 + ng * 16 + rr) * 128 + uu * 16));
#pragma unroll
            for (int mt = 0; mt < 2; ++mt)
#pragma unroll
                for (int ng = 0; ng < 4; ++ng) {
                    mma16816(c[mt][ng * 2],     afr[mt], bfr[ng][0], bfr[ng][2]);
                    mma16816(c[mt][ng * 2 + 1], afr[mt], bfr[ng][1], bfr[ng][3]);
                }
        }
        __syncthreads();
    }
#undef PREFETCH

    // ---------------- epilogues ----------------
    if (mode == 2) {
        // V: stage transposed fp16 in smem, then coalesced store to [bh][d][s]
#pragma unroll
        for (int mt = 0; mt < 2; ++mt) {
            int mrow = wm * 32 + mt * 16 + (lane >> 2);
#pragma unroll
            for (int nt = 0; nt < 8; ++nt) {
                int nl = wn * 64 + nt * 8 + (lane & 3) * 2;
                float b0 = bias[n0 + nl], b1 = bias[n0 + nl + 1];
#pragma unroll
                for (int half = 0; half < 2; ++half) {
                    int ml = mrow + half * 8;
                    *(__half*)(smem + nl * 256 + ml * 2) =
                        __float2half_rn(c[mt][nt][half * 2] + b0);
                    *(__half*)(smem + (nl + 1) * 256 + ml * 2) =
                        __float2half_rn(c[mt][nt][half * 2 + 1] + b1);
                }
            }
        }
        __syncthreads();
        int bq = m0 >> 11, sq = m0 & 2047;
        int hbase = n0 >> 6;
        for (int cidx = tid; cidx < 2048; cidx += 256) {
            int nn = cidx >> 4, mc = cidx & 15;
            uint4 hv = *(uint4*)(smem + nn * 256 + mc * 16);
            size_t o = (((size_t)(bq * NH + hbase + (nn >> 6)) * HD + (nn & 63)) * SEQ
                        + sq + mc * 8);
            *(uint4*)&g_vth[o] = hv;
        }
        return;
    }

#pragma unroll
    for (int mt = 0; mt < 2; ++mt) {
        int row0 = wm * 32 + mt * 16 + (lane >> 2);
#pragma unroll
        for (int nt = 0; nt < 8; ++nt) {
            int n = n0 + wn * 64 + nt * 8 + (lane & 3) * 2;
            float b0 = bias[n], b1 = bias[n + 1];
#pragma unroll
            for (int half = 0; half < 2; ++half) {
                int m = m0 + row0 + half * 8;
                int b = m >> 11, s = m & 2047;
                float v0 = c[mt][nt][half * 2] + b0;
                float v1 = c[mt][nt][half * 2 + 1] + b1;
                if (mode == 3) {
                    *(float2*)&out[(size_t)m * EMB + n] = make_float2(v0, v1);
                } else {
                    const float sc0 = (mode == 0) ? 0.18033688f : 1.0f;  // 1.442695/8
                    v0 *= g_adapt[b * EMB + n] * sc0;
                    v1 *= g_adapt[b * EMB + n + 1] * sc0;
                    int h = n >> 6, d = n & 63;
                    size_t o = ((size_t)(b * NH + h) * SEQ + s) * HD + d;
                    uint32_t hp = pack_h2(v0, v1);
                    if (mode == 0) *(uint32_t*)&g_qh[o] = hp;
                    else           *(uint32_t*)&g_kh[o] = hp;
                }
            }
        }
    }
}

// ---------------------------------------------------------------------------
// Kernel: tensor-core flash attention, fp16 single-term, P in registers.
// ---------------------------------------------------------------------------
__global__ void __launch_bounds__(256)
flash_tc()
{
    extern __shared__ __align__(1024) char smem[];
    const uint32_t sb = smem_u32(smem);
    const int tid = threadIdx.x, lane = tid & 31, wid = tid >> 5;
    const int wm = wid >> 1, wn = wid & 1;
    const int s0 = blockIdx.x * 128;
    const int h  = blockIdx.y, b = blockIdx.z;
    const int bh = b * NH + h;
    const int rr = lane & 15;

    if (tid < 128) *(float*)(smem + FLSM + tid * 4) = 0.f;

    const __half* qh  = g_qh + ((size_t)bh * SEQ + s0) * HD;
    const __half* kh  = g_kh + (size_t)bh * SEQ * HD;
    const __half* vth = g_vth + (size_t)bh * HD * SEQ;

    // Q tile (once): 128 rows x 128 B
#pragma unroll
    for (int i = 0; i < 4; ++i) {
        int idx = tid + i * 256;       // 0..1023
        int r = idx >> 3, u = idx & 7;
        cp16(sb + FQ + SWZ128(r * 128 + u * 16), qh + r * HD + u * 8);
    }
    asm volatile("cp.async.commit_group;");

#define KVPRE(kb)                                                                       \
    do {                                                                                \
        uint32_t st = sb + FKV + ((kb) & 1) * FSTG;                                     \
        _Pragma("unroll")                                                               \
        for (int i = 0; i < 2; ++i) {                                                   \
            int idx = tid + i * 256;     /* 0..511 */                                   \
            int r = idx >> 3, u = idx & 7;                                              \
            uint32_t sw = SWZ128(r * 128 + u * 16);                                     \
            cp16(st + sw,        kh + ((size_t)(kb) * 64 + r) * HD + u * 8);            \
            cp16(st + 8192 + sw, vth + (size_t)r * SEQ + (kb) * 64 + u * 8);            \
        }                                                                               \
        asm volatile("cp.async.commit_group;");                                         \
    } while (0)

    KVPRE(0);

    float oc[2][8][4];
#pragma unroll
    for (int a = 0; a < 2; ++a)
#pragma unroll
        for (int f = 0; f < 8; ++f)
#pragma unroll
            for (int d = 0; d < 4; ++d) oc[a][f][d] = 0.f;
    float l_part[4] = {0.f, 0.f, 0.f, 0.f};

#pragma unroll 1
    for (int kb = 0; kb < SEQ / 64; ++kb) {
        asm volatile("cp.async.wait_group 0;");
        __syncthreads();
        if (kb + 1 < SEQ / 64) KVPRE(kb + 1);

        const uint32_t stg = sb + FKV + (kb & 1) * FSTG;

        // ---- S = Q K^T (fp16 single term) ----
        float sc[2][4][4];
#pragma unroll
        for (int a = 0; a < 2; ++a)
#pragma unroll
            for (int f = 0; f < 4; ++f)
#pragma unroll
                for (int d = 0; d < 4; ++d) sc[a][f][d] = 0.f;

#pragma unroll
        for (int ks = 0; ks < 4; ++ks) {
            const int uu = 2 * ks + (lane >> 4);
            uint32_t aH[2][4], bH[2][4];
#pragma unroll
            for (int mt = 0; mt < 2; ++mt)
                ldm4(aH[mt], sb + FQ + SWZ128((wm * 32 + mt * 16 + rr) * 128 + uu * 16));
#pragma unroll
            for (int ng = 0; ng < 2; ++ng)
                ldm4(bH[ng], stg + SWZ128((wn * 32 + ng * 16 + rr) * 128 + uu * 16));
#pragma unroll
            for (int mt = 0; mt < 2; ++mt)
#pragma unroll
                for (int ng = 0; ng < 2; ++ng) {
                    mma16816(sc[mt][ng * 2],     aH[mt], bH[ng][0], bH[ng][2]);
                    mma16816(sc[mt][ng * 2 + 1], aH[mt], bH[ng][1], bH[ng][3]);
                }
        }

        // ---- p = 2^s; pack fp16 A-fragments in registers ----
        uint32_t pA[2][4], pB[2][4];
#pragma unroll
        for (int mt = 0; mt < 2; ++mt)
#pragma unroll
            for (int nf = 0; nf < 4; ++nf) {
                float p0 = fast_ex2(sc[mt][nf][0]);
                float p1 = fast_ex2(sc[mt][nf][1]);
                float p2 = fast_ex2(sc[mt][nf][2]);
                float p3 = fast_ex2(sc[mt][nf][3]);
                l_part[mt * 2 + 0] += p0 + p1;
                l_part[mt * 2 + 1] += p2 + p3;
                pA[mt][nf] = pack_h2(p0, p1);
                pB[mt][nf] = pack_h2(p2, p3);
            }

        // ---- O_partial += P V over this warp's 32 keys, all 64 d ----
#pragma unroll
        for (int ksp = 0; ksp < 2; ++ksp) {
            const int uu = 2 * (wn * 2 + ksp) + (lane >> 4);
            uint32_t bV[4][4];
#pragma unroll
            for (int g = 0; g < 4; ++g)
                ldm4(bV[g], stg + 8192 + SWZ128((g * 16 + rr) * 128 + uu * 16));
#pragma unroll
            for (int mt = 0; mt < 2; ++mt) {
                uint32_t aP[4] = {pA[mt][2 * ksp], pB[mt][2 * ksp],
                                  pA[mt][2 * ksp + 1], pB[mt][2 * ksp + 1]};
#pragma unroll
                for (int g = 0; g < 4; ++g) {
                    mma16816(oc[mt][2 * g],     aP, bV[g][0], bV[g][2]);
                    mma16816(oc[mt][2 * g + 1], aP, bV[g][1], bV[g][3]);
                }
            }
        }
    }
#undef KVPRE

    // ---- reduce l across the 4 lanes of each row-group ----
#pragma unroll
    for (int j = 0; j < 4; ++j) {
        l_part[j] += __shfl_xor_sync(0xFFFFFFFF, l_part[j], 1);
        l_part[j] += __shfl_xor_sync(0xFFFFFFFF, l_part[j], 2);
    }
    if ((lane & 3) == 0) {
#pragma unroll
        for (int mt = 0; mt < 2; ++mt)
#pragma unroll
            for (int half = 0; half < 2; ++half) {
                int r = wm * 32 + mt * 16 + (lane >> 2) + half * 8;
                atomicAdd((float*)(smem + FLSM + r * 4), l_part[mt * 2 + half]);
            }
    }
    __syncthreads();   // all PV done; Q + stage0 now dead -> O reduce buffer (32 KB)

    if (wn == 1) {
#pragma unroll
        for (int mt = 0; mt < 2; ++mt) {
            int row = wm * 32 + mt * 16 + (lane >> 2);
#pragma unroll
            for (int nf = 0; nf < 8; ++nf) {
                int col = nf * 8 + (lane & 3) * 2;
                *(float2*)(smem + (row * 64 + col) * 4) =
                    make_float2(oc[mt][nf][0], oc[mt][nf][1]);
                *(float2*)(smem + ((row + 8) * 64 + col) * 4) =
                    make_float2(oc[mt][nf][2], oc[mt][nf][3]);
            }
        }
    }
    __syncthreads();

    if (wn == 0) {
#pragma unroll
        for (int mt = 0; mt < 2; ++mt)
#pragma unroll
            for (int half = 0; half < 2; ++half) {
                int r = wm * 32 + mt * 16 + (lane >> 2) + half * 8;
                float inv = 1.f / *(float*)(smem + FLSM + r * 4);
                size_t mrow = (size_t)(b * SEQ + s0 + r) * EMB;
#pragma unroll
                for (int nf = 0; nf < 8; ++nf) {
                    int col = nf * 8 + (lane & 3) * 2;
                    float2 part = *(float2*)(smem + (r * 64 + col) * 4);
                    float v0 = (oc[mt][nf][half * 2]     + part.x) * inv;
                    float v1 = (oc[mt][nf][half * 2 + 1] + part.y) * inv;
                    *(uint32_t*)&g_ah[mrow + h * HD + col] = pack_h2(v0, v1);
                }
            }
    }
}

// ---------------------------------------------------------------------------
// Launch
// ---------------------------------------------------------------------------
extern "C" void kernel_launch(void* const* d_in, const int* in_sizes, int n_in,
                              void* d_out, int out_size)
{
    const float* query = (const float*)d_in[0];
    const float* xi    = (const float*)d_in[1];
    const float* Wq    = (const float*)d_in[2];
    const float* bq    = (const float*)d_in[3];
    const float* Wk    = (const float*)d_in[4];
    const float* bk    = (const float*)d_in[5];
    const float* Wv    = (const float*)d_in[6];
    const float* bv    = (const float*)d_in[7];
    const float* Wo    = (const float*)d_in[8];
    const float* bo    = (const float*)d_in[9];
    const float* ew1   = (const float*)d_in[10];
    const float* eb1   = (const float*)d_in[11];
    const float* lng   = (const float*)d_in[12];
    const float* lnb   = (const float*)d_in[13];
    const float* ew2   = (const float*)d_in[14];
    const float* eb2   = (const float*)d_in[15];
    const float* gate  = (const float*)d_in[16];
    float* out = (float*)d_out;

    // Idempotent, capture-safe, no static guard (harness rule).
    cudaFuncSetAttribute(gemm_mma, cudaFuncAttributeMaxDynamicSharedMemorySize, GEMM_SMEM);
    cudaFuncSetAttribute(flash_tc, cudaFuncAttributeMaxDynamicSharedMemorySize, FLASH_SMEM);

    int nX = M_TOT * EMB;
    __half *xh, *ah, *w2;
    cudaGetSymbolAddress((void**)&xh, g_xh);
    cudaGetSymbolAddress((void**)&ah, g_ah);
    cudaGetSymbolAddress((void**)&w2, g_w2);

    dim3 wgrid(EMB / 32, EMB / 32), wblk(32, 8);
    dim3 ggrid(EMB / TN, M_TOT / TM);

    adapt_kernel<<<1, 32>>>(xi, ew1, eb1, lng, lnb, ew2, eb2, gate);
    half_kernel<<<nX / 256, 256>>>(query, xh, nX);
    wsplit2_kernel<<<wgrid, wblk>>>(Wq, w2 + (size_t)0 * EMB * K2);
    wsplit2_kernel<<<wgrid, wblk>>>(Wk, w2 + (size_t)1 * EMB * K2);
    wsplit2_kernel<<<wgrid, wblk>>>(Wv, w2 + (size_t)2 * EMB * K2);
    gemm_mma<<<ggrid, 256, GEMM_SMEM>>>(xh, w2 + (size_t)0 * EMB * K2, bq, out, 0);
    gemm_mma<<<ggrid, 256, GEMM_SMEM>>>(xh, w2 + (size_t)1 * EMB * K2, bk, out, 1);
    gemm_mma<<<ggrid, 256, GEMM_SMEM>>>(xh, w2 + (size_t)2 * EMB * K2, bv, out, 2);
    wsplit2_kernel<<<wgrid, wblk>>>(Wo, w2 + (size_t)3 * EMB * K2);
    flash_tc<<<dim3(SEQ / 128, NH, BATCH), 256, FLASH_SMEM>>>();
    gemm_mma<<<ggrid, 256, GEMM_SMEM>>>(ah, w2 + (size_t)3 * EMB * K2, bo, out, 3);
}

// round 12
// speedup vs baseline: 1.8691x; 1.0153x over previous
#include <cuda_runtime.h>
#include <cuda_fp16.h>
#include <cstdint>
#include <math.h>

// Problem constants
constexpr int BATCH = 2;
constexpr int SEQ   = 2048;
constexpr int EMB   = 1024;
constexpr int NH    = 16;
constexpr int HD    = 64;
constexpr int HD2   = 32;
constexpr int M_TOT = BATCH * SEQ;   // 4096

// GEMM tiling (mma.sync fp16; A = x (K=1024, reused for both halves),
// B = [Whi | Wlo] (K2=2048))
constexpr int TM  = 128;
constexpr int TN  = 128;
constexpr int K2  = 2 * EMB;          // 2048
constexpr int KC  = 64;               // fp16 per chunk = 128 B rows
constexpr int NCH = K2 / KC;          // 32
constexpr int STAGE_BYTES = 2 * TM * 128;          // A tile + B tile = 32 KB
constexpr uint32_t GEMM_SMEM = 2 * STAGE_BYTES;    // 64 KB

// Flash smem layout (bytes)
constexpr uint32_t FQ   = 0;           // 16 KB q fp16 (reused for O-reduce)
constexpr uint32_t FKV  = 16384;       // 2 stages x 16 KB (K 8K, V 8K)
constexpr uint32_t FSTG = 16384;
constexpr uint32_t FLSM = 49152;       // 512 B for l
constexpr uint32_t FLASH_SMEM = 49152 + 512;

// ---------------------------------------------------------------------------
// Scratch (device globals -- no runtime allocation allowed)
// ---------------------------------------------------------------------------
__device__ float g_adapt[BATCH * EMB];

__device__ __half g_xh[(size_t)M_TOT * EMB];        // x rounded to fp16
__device__ __half g_ah[(size_t)M_TOT * EMB];        // attention out fp16
__device__ __half g_w2[4][(size_t)EMB * K2];        // transposed [n][whi | wlo]

__device__ __half g_qh[(size_t)BATCH * NH * SEQ * HD];  // [bh][s][d]
__device__ __half g_kh[(size_t)BATCH * NH * SEQ * HD];
__device__ __half g_vth[(size_t)BATCH * NH * HD * SEQ]; // [bh][d][s]

// ---------------------------------------------------------------------------
// Helpers
// ---------------------------------------------------------------------------
__device__ __forceinline__ uint32_t smem_u32(const void* p) {
    uint32_t a;
    asm("{ .reg .u64 t; cvta.to.shared.u64 t, %1; cvt.u32.u64 %0, t; }" : "=r"(a) : "l"(p));
    return a;
}
#define SWZ128(off) ((off) ^ (((off) >> 3) & 0x70))

__device__ __forceinline__ void cp16(uint32_t d, const void* g) {
    asm volatile("cp.async.cg.shared.global [%0], [%1], 16;" :: "r"(d), "l"(g));
}
__device__ __forceinline__ void ldm4(uint32_t* f, uint32_t addr) {
    asm volatile("ldmatrix.sync.aligned.m8n8.x4.shared.b16 {%0,%1,%2,%3}, [%4];"
        : "=r"(f[0]), "=r"(f[1]), "=r"(f[2]), "=r"(f[3]) : "r"(addr));
}
__device__ __forceinline__ void mma16816(float* c, const uint32_t* a, uint32_t b0, uint32_t b1) {
    asm volatile("mma.sync.aligned.m16n8k16.row.col.f32.f16.f16.f32 "
        "{%0,%1,%2,%3}, {%4,%5,%6,%7}, {%8,%9}, {%0,%1,%2,%3};"
        : "+f"(c[0]), "+f"(c[1]), "+f"(c[2]), "+f"(c[3])
        : "r"(a[0]), "r"(a[1]), "r"(a[2]), "r"(a[3]), "r"(b0), "r"(b1));
}
__device__ __forceinline__ float fast_ex2(float x) {
    float y; asm("ex2.approx.f32 %0, %1;" : "=f"(y) : "f"(x)); return y;
}
__device__ __forceinline__ uint32_t pack_h2(float a, float b) {
    __half2 t = __floats2half2_rn(a, b);
    uint32_t r;
    memcpy(&r, &t, 4);
    return r;
}

// ---------------------------------------------------------------------------
// Kernel: adapt
// ---------------------------------------------------------------------------
__global__ void adapt_kernel(const float* __restrict__ xi,
                             const float* __restrict__ ew1, const float* __restrict__ eb1,
                             const float* __restrict__ lng, const float* __restrict__ lnb,
                             const float* __restrict__ ew2, const float* __restrict__ eb2,
                             const float* __restrict__ gate)
{
    int b = threadIdx.x;
    if (b >= BATCH) return;
    float x[HD2];
    float xv = xi[b];
    float mu = 0.f;
#pragma unroll
    for (int i = 0; i < HD2; ++i) { x[i] = xv * ew1[i] + eb1[i]; mu += x[i]; }
    mu *= (1.0f / HD2);
    float var = 0.f;
#pragma unroll
    for (int i = 0; i < HD2; ++i) { float d = x[i] - mu; var += d * d; }
    var *= (1.0f / HD2);
    float rs = rsqrtf(var + 1e-5f);
#pragma unroll
    for (int i = 0; i < HD2; ++i) {
        float xn = (x[i] - mu) * rs * lng[i] + lnb[i];
        x[i] = 0.5f * xn * (1.f + erff(xn * 0.70710678118654752f));
    }
    float sg[NH];
#pragma unroll
    for (int h = 0; h < NH; ++h) sg[h] = 1.f / (1.f + expf(-gate[h]));
    for (int d = 0; d < HD; ++d) {
        float xe = eb2[d];
#pragma unroll
        for (int i = 0; i < HD2; ++i) xe += x[i] * ew2[i * HD + d];
#pragma unroll
        for (int h = 0; h < NH; ++h)
            g_adapt[b * EMB + h * HD + d] = 1.f + sg[h] * xe;
    }
}

// ---------------------------------------------------------------------------
// Kernel: fp32 -> fp16 (plain)
// ---------------------------------------------------------------------------
__global__ void __launch_bounds__(256)
half_kernel(const float* __restrict__ in, __half* __restrict__ out, int n)
{
    int i = blockIdx.x * 256 + threadIdx.x;
    if (i < n) out[i] = __float2half_rn(in[i]);
}

// ---------------------------------------------------------------------------
// Kernel: all four W[K,N] fp32 -> transposed fp16 [N, 2048] = [hi | lo]
// blockIdx.z selects the weight matrix.
// ---------------------------------------------------------------------------
__global__ void __launch_bounds__(256)
wsplit2_all(const float* __restrict__ Wq, const float* __restrict__ Wk,
            const float* __restrict__ Wv, const float* __restrict__ Wo,
            __half* __restrict__ w2base)
{
    const float* W = (blockIdx.z == 0) ? Wq : (blockIdx.z == 1) ? Wk
                   : (blockIdx.z == 2) ? Wv : Wo;
    __half* out2 = w2base + (size_t)blockIdx.z * EMB * K2;

    __shared__ float t[32][33];
    int n0 = blockIdx.x * 32, k0 = blockIdx.y * 32;
    int tx = threadIdx.x, ty = threadIdx.y;   // (32, 8)
#pragma unroll
    for (int i = 0; i < 32; i += 8)
        t[ty + i][tx] = W[(size_t)(k0 + ty + i) * EMB + n0 + tx];
    __syncthreads();
#pragma unroll
    for (int i = 0; i < 32; i += 8) {
        float x = t[tx][ty + i];              // k=k0+tx, n=n0+ty+i
        __half h = __float2half_rn(x);
        __half l = __float2half_rn(x - __half2float(h));
        size_t base = (size_t)(n0 + ty + i) * K2 + k0 + tx;
        out2[base]       = h;
        out2[base + EMB] = l;
    }
}

// ---------------------------------------------------------------------------
// Kernel: mma.sync fp16 GEMM  C[M,N] = A[M,1024] * ([Whi|Wlo])[N,2048]^T + bias
// A is read twice (chunks 0..15 and 16..31 both map to x's K range).
// mode = mode_base + blockIdx.z:
//   0: Q -> *adapt*(log2e/8) -> g_qh   1: K -> *adapt -> g_kh
//   2: V -> transpose -> g_vth          3: O -> out fp32
// ---------------------------------------------------------------------------
__global__ void __launch_bounds__(256)
gemm_mma(const __half* __restrict__ Ah, const __half* __restrict__ w2base,
         const float* __restrict__ bq, const float* __restrict__ bk,
         const float* __restrict__ bv, const float* __restrict__ bo,
         float* __restrict__ out, int mode_base)
{
    extern __shared__ __align__(1024) char smem[];
    const uint32_t sb = smem_u32(smem);
    const int tid  = threadIdx.x;
    const int lane = tid & 31;
    const int wid  = tid >> 5;
    const int wm   = wid >> 1;        // 0..3
    const int wn   = wid & 1;         // 0..1
    const int m0 = blockIdx.y * TM;
    const int n0 = blockIdx.x * TN;
    const int mode = mode_base + blockIdx.z;

    const float* bias = (mode == 0) ? bq : (mode == 1) ? bk : (mode == 2) ? bv : bo;
    const __half* Ab = Ah + (size_t)m0 * EMB;
    const __half* Bb = w2base + (size_t)mode * EMB * K2 + (size_t)n0 * K2;

    float c[2][8][4];
#pragma unroll
    for (int a = 0; a < 2; ++a)
#pragma unroll
        for (int b = 0; b < 8; ++b)
#pragma unroll
            for (int d = 0; d < 4; ++d) c[a][b][d] = 0.f;

#define PREFETCH(kc)                                                                   \
    do {                                                                               \
        uint32_t st = sb + ((kc) & 1) * STAGE_BYTES;                                   \
        int ka = ((kc) & 15) * KC;                                                     \
        _Pragma("unroll")                                                              \
        for (int i = 0; i < 4; ++i) {                                                  \
            int idx = tid + i * 256;                                                   \
            int r = idx >> 3, u = idx & 7;                                             \
            cp16(st + SWZ128(r * 128 + u * 16), Ab + (size_t)r * EMB + ka + u * 8);    \
            cp16(st + TM * 128 + SWZ128(r * 128 + u * 16),                             \
                 Bb + (size_t)r * K2 + (kc) * KC + u * 8);                             \
        }                                                                              \
        asm volatile("cp.async.commit_group;");                                        \
    } while (0)

    PREFETCH(0);

    for (int kc = 0; kc < NCH; ++kc) {
        if (kc + 1 < NCH) {
            PREFETCH(kc + 1);
            asm volatile("cp.async.wait_group 1;");
        } else {
            asm volatile("cp.async.wait_group 0;");
        }
        __syncthreads();

        const uint32_t sA = sb + (kc & 1) * STAGE_BYTES;
        const uint32_t sB = sA + TM * 128;
        const int rr = lane & 15;

#pragma unroll
        for (int ks = 0; ks < 4; ++ks) {
            const int uu = 2 * ks + (lane >> 4);
            uint32_t afr[2][4], bfr[4][4];
#pragma unroll
            for (int mt = 0; mt < 2; ++mt)
                ldm4(afr[mt], sA + SWZ128((wm * 32 + mt * 16 + rr) * 128 + uu * 16));
#pragma unroll
            for (int ng = 0; ng < 4; ++ng)
                ldm4(bfr[ng], sB + SWZ128((wn * 64 + ng * 16 + rr) * 128 + uu * 16));
#pragma unroll
            for (int mt = 0; mt < 2; ++mt)
#pragma unroll
                for (int ng = 0; ng < 4; ++ng) {
                    mma16816(c[mt][ng * 2],     afr[mt], bfr[ng][0], bfr[ng][2]);
                    mma16816(c[mt][ng * 2 + 1], afr[mt], bfr[ng][1], bfr[ng][3]);
                }
        }
        __syncthreads();
    }
#undef PREFETCH

    // ---------------- epilogues ----------------
    if (mode == 2) {
        // V: stage transposed fp16 in smem, then coalesced store to [bh][d][s]
#pragma unroll
        for (int mt = 0; mt < 2; ++mt) {
            int mrow = wm * 32 + mt * 16 + (lane >> 2);
#pragma unroll
            for (int nt = 0; nt < 8; ++nt) {
                int nl = wn * 64 + nt * 8 + (lane & 3) * 2;
                float b0 = bias[n0 + nl], b1 = bias[n0 + nl + 1];
#pragma unroll
                for (int half = 0; half < 2; ++half) {
                    int ml = mrow + half * 8;
                    *(__half*)(smem + nl * 256 + ml * 2) =
                        __float2half_rn(c[mt][nt][half * 2] + b0);
                    *(__half*)(smem + (nl + 1) * 256 + ml * 2) =
                        __float2half_rn(c[mt][nt][half * 2 + 1] + b1);
                }
            }
        }
        __syncthreads();
        int bq2 = m0 >> 11, sq = m0 & 2047;
        int hbase = n0 >> 6;
        for (int cidx = tid; cidx < 2048; cidx += 256) {
            int nn = cidx >> 4, mc = cidx & 15;
            uint4 hv = *(uint4*)(smem + nn * 256 + mc * 16);
            size_t o = (((size_t)(bq2 * NH + hbase + (nn >> 6)) * HD + (nn & 63)) * SEQ
                        + sq + mc * 8);
            *(uint4*)&g_vth[o] = hv;
        }
        return;
    }

#pragma unroll
    for (int mt = 0; mt < 2; ++mt) {
        int row0 = wm * 32 + mt * 16 + (lane >> 2);
#pragma unroll
        for (int nt = 0; nt < 8; ++nt) {
            int n = n0 + wn * 64 + nt * 8 + (lane & 3) * 2;
            float b0 = bias[n], b1 = bias[n + 1];
#pragma unroll
            for (int half = 0; half < 2; ++half) {
                int m = m0 + row0 + half * 8;
                int b = m >> 11, s = m & 2047;
                float v0 = c[mt][nt][half * 2] + b0;
                float v1 = c[mt][nt][half * 2 + 1] + b1;
                if (mode == 3) {
                    *(float2*)&out[(size_t)m * EMB + n] = make_float2(v0, v1);
                } else {
                    const float sc0 = (mode == 0) ? 0.18033688f : 1.0f;  // 1.442695/8
                    v0 *= g_adapt[b * EMB + n] * sc0;
                    v1 *= g_adapt[b * EMB + n + 1] * sc0;
                    int h = n >> 6, d = n & 63;
                    size_t o = ((size_t)(b * NH + h) * SEQ + s) * HD + d;
                    uint32_t hp = pack_h2(v0, v1);
                    if (mode == 0) *(uint32_t*)&g_qh[o] = hp;
                    else           *(uint32_t*)&g_kh[o] = hp;
                }
            }
        }
    }
}

// ---------------------------------------------------------------------------
// Kernel: tensor-core flash attention, fp16 single-term, P in registers,
// Q fragments hoisted out of the K-loop.
// ---------------------------------------------------------------------------
__global__ void __launch_bounds__(256)
flash_tc()
{
    extern __shared__ __align__(1024) char smem[];
    const uint32_t sb = smem_u32(smem);
    const int tid = threadIdx.x, lane = tid & 31, wid = tid >> 5;
    const int wm = wid >> 1, wn = wid & 1;
    const int s0 = blockIdx.x * 128;
    const int h  = blockIdx.y, b = blockIdx.z;
    const int bh = b * NH + h;
    const int rr = lane & 15;

    if (tid < 128) *(float*)(smem + FLSM + tid * 4) = 0.f;

    const __half* qh  = g_qh + ((size_t)bh * SEQ + s0) * HD;
    const __half* kh  = g_kh + (size_t)bh * SEQ * HD;
    const __half* vth = g_vth + (size_t)bh * HD * SEQ;

    // Q tile + first KV stage
#pragma unroll
    for (int i = 0; i < 4; ++i) {
        int idx = tid + i * 256;       // 0..1023
        int r = idx >> 3, u = idx & 7;
        cp16(sb + FQ + SWZ128(r * 128 + u * 16), qh + r * HD + u * 8);
    }
    asm volatile("cp.async.commit_group;");

#define KVPRE(kb)                                                                       \
    do {                                                                                \
        uint32_t st = sb + FKV + ((kb) & 1) * FSTG;                                     \
        _Pragma("unroll")                                                               \
        for (int i = 0; i < 2; ++i) {                                                   \
            int idx = tid + i * 256;     /* 0..511 */                                   \
            int r = idx >> 3, u = idx & 7;                                              \
            uint32_t sw = SWZ128(r * 128 + u * 16);                                     \
            cp16(st + sw,        kh + ((size_t)(kb) * 64 + r) * HD + u * 8);            \
            cp16(st + 8192 + sw, vth + (size_t)r * SEQ + (kb) * 64 + u * 8);            \
        }                                                                               \
        asm volatile("cp.async.commit_group;");                                         \
    } while (0)

    KVPRE(0);
    asm volatile("cp.async.wait_group 0;");
    __syncthreads();

    // hoist Q fragments (loop-invariant): qf[ks][mt][4]
    uint32_t qf[4][2][4];
#pragma unroll
    for (int ks = 0; ks < 4; ++ks) {
        const int uu = 2 * ks + (lane >> 4);
#pragma unroll
        for (int mt = 0; mt < 2; ++mt)
            ldm4(qf[ks][mt], sb + FQ + SWZ128((wm * 32 + mt * 16 + rr) * 128 + uu * 16));
    }

    float oc[2][8][4];
#pragma unroll
    for (int a = 0; a < 2; ++a)
#pragma unroll
        for (int f = 0; f < 8; ++f)
#pragma unroll
            for (int d = 0; d < 4; ++d) oc[a][f][d] = 0.f;
    float l_part[4] = {0.f, 0.f, 0.f, 0.f};

#pragma unroll 1
    for (int kb = 0; kb < SEQ / 64; ++kb) {
        if (kb + 1 < SEQ / 64) KVPRE(kb + 1);

        const uint32_t stg = sb + FKV + (kb & 1) * FSTG;

        // ---- S = Q K^T (fp16 single term) ----
        float sc[2][4][4];
#pragma unroll
        for (int a = 0; a < 2; ++a)
#pragma unroll
            for (int f = 0; f < 4; ++f)
#pragma unroll
                for (int d = 0; d < 4; ++d) sc[a][f][d] = 0.f;

#pragma unroll
        for (int ks = 0; ks < 4; ++ks) {
            const int uu = 2 * ks + (lane >> 4);
            uint32_t bH[2][4];
#pragma unroll
            for (int ng = 0; ng < 2; ++ng)
                ldm4(bH[ng], stg + SWZ128((wn * 32 + ng * 16 + rr) * 128 + uu * 16));
#pragma unroll
            for (int mt = 0; mt < 2; ++mt)
#pragma unroll
                for (int ng = 0; ng < 2; ++ng) {
                    mma16816(sc[mt][ng * 2],     qf[ks][mt], bH[ng][0], bH[ng][2]);
                    mma16816(sc[mt][ng * 2 + 1], qf[ks][mt], bH[ng][1], bH[ng][3]);
                }
        }

        // ---- p = 2^s; pack fp16 A-fragments in registers ----
        uint32_t pA[2][4], pB[2][4];
#pragma unroll
        for (int mt = 0; mt < 2; ++mt)
#pragma unroll
            for (int nf = 0; nf < 4; ++nf) {
                float p0 = fast_ex2(sc[mt][nf][0]);
                float p1 = fast_ex2(sc[mt][nf][1]);
                float p2 = fast_ex2(sc[mt][nf][2]);
                float p3 = fast_ex2(sc[mt][nf][3]);
                l_part[mt * 2 + 0] += p0 + p1;
                l_part[mt * 2 + 1] += p2 + p3;
                pA[mt][nf] = pack_h2(p0, p1);
                pB[mt][nf] = pack_h2(p2, p3);
            }

        // ---- O_partial += P V over this warp's 32 keys, all 64 d ----
#pragma unroll
        for (int ksp = 0; ksp < 2; ++ksp) {
            const int uu = 2 * (wn * 2 + ksp) + (lane >> 4);
            uint32_t bV[4][4];
#pragma unroll
            for (int g = 0; g < 4; ++g)
                ldm4(bV[g], stg + 8192 + SWZ128((g * 16 + rr) * 128 + uu * 16));
#pragma unroll
            for (int mt = 0; mt < 2; ++mt) {
                uint32_t aP[4] = {pA[mt][2 * ksp], pB[mt][2 * ksp],
                                  pA[mt][2 * ksp + 1], pB[mt][2 * ksp + 1]};
#pragma unroll
                for (int g = 0; g < 4; ++g) {
                    mma16816(oc[mt][2 * g],     aP, bV[g][0], bV[g][2]);
                    mma16816(oc[mt][2 * g + 1], aP, bV[g][1], bV[g][3]);
                }
            }
        }

        // stage kb fully consumed; wait for kb+1 data and make write-safe
        if (kb + 1 < SEQ / 64) {
            asm volatile("cp.async.wait_group 0;");
            __syncthreads();
        }
    }
#undef KVPRE

    // ---- reduce l across the 4 lanes of each row-group ----
#pragma unroll
    for (int j = 0; j < 4; ++j) {
        l_part[j] += __shfl_xor_sync(0xFFFFFFFF, l_part[j], 1);
        l_part[j] += __shfl_xor_sync(0xFFFFFFFF, l_part[j], 2);
    }
    if ((lane & 3) == 0) {
#pragma unroll
        for (int mt = 0; mt < 2; ++mt)
#pragma unroll
            for (int half = 0; half < 2; ++half) {
                int r = wm * 32 + mt * 16 + (lane >> 2) + half * 8;
                atomicAdd((float*)(smem + FLSM + r * 4), l_part[mt * 2 + half]);
            }
    }
    __syncthreads();   // all PV done; Q area now dead -> O reduce buffer (32 KB)

    if (wn == 1) {
#pragma unroll
        for (int mt = 0; mt < 2; ++mt) {
            int row = wm * 32 + mt * 16 + (lane >> 2);
#pragma unroll
            for (int nf = 0; nf < 8; ++nf) {
                int col = nf * 8 + (lane & 3) * 2;
                *(float2*)(smem + (row * 64 + col) * 4) =
                    make_float2(oc[mt][nf][0], oc[mt][nf][1]);
                *(float2*)(smem + ((row + 8) * 64 + col) * 4) =
                    make_float2(oc[mt][nf][2], oc[mt][nf][3]);
            }
        }
    }
    __syncthreads();

    if (wn == 0) {
#pragma unroll
        for (int mt = 0; mt < 2; ++mt)
#pragma unroll
            for (int half = 0; half < 2; ++half) {
                int r = wm * 32 + mt * 16 + (lane >> 2) + half * 8;
                float inv = 1.f / *(float*)(smem + FLSM + r * 4);
                size_t mrow = (size_t)(b * SEQ + s0 + r) * EMB;
#pragma unroll
                for (int nf = 0; nf < 8; ++nf) {
                    int col = nf * 8 + (lane & 3) * 2;
                    float2 part = *(float2*)(smem + (r * 64 + col) * 4);
                    float v0 = (oc[mt][nf][half * 2]     + part.x) * inv;
                    float v1 = (oc[mt][nf][half * 2 + 1] + part.y) * inv;
                    *(uint32_t*)&g_ah[mrow + h * HD + col] = pack_h2(v0, v1);
                }
            }
    }
}

// ---------------------------------------------------------------------------
// Launch
// ---------------------------------------------------------------------------
extern "C" void kernel_launch(void* const* d_in, const int* in_sizes, int n_in,
                              void* d_out, int out_size)
{
    const float* query = (const float*)d_in[0];
    const float* xi    = (const float*)d_in[1];
    const float* Wq    = (const float*)d_in[2];
    const float* bq    = (const float*)d_in[3];
    const float* Wk    = (const float*)d_in[4];
    const float* bk    = (const float*)d_in[5];
    const float* Wv    = (const float*)d_in[6];
    const float* bv    = (const float*)d_in[7];
    const float* Wo    = (const float*)d_in[8];
    const float* bo    = (const float*)d_in[9];
    const float* ew1   = (const float*)d_in[10];
    const float* eb1   = (const float*)d_in[11];
    const float* lng   = (const float*)d_in[12];
    const float* lnb   = (const float*)d_in[13];
    const float* ew2   = (const float*)d_in[14];
    const float* eb2   = (const float*)d_in[15];
    const float* gate  = (const float*)d_in[16];
    float* out = (float*)d_out;

    // Idempotent, capture-safe, no static guard (harness rule).
    cudaFuncSetAttribute(gemm_mma, cudaFuncAttributeMaxDynamicSharedMemorySize, GEMM_SMEM);
    cudaFuncSetAttribute(flash_tc, cudaFuncAttributeMaxDynamicSharedMemorySize, FLASH_SMEM);

    int nX = M_TOT * EMB;
    __half *xh, *ah, *w2;
    cudaGetSymbolAddress((void**)&xh, g_xh);
    cudaGetSymbolAddress((void**)&ah, g_ah);
    cudaGetSymbolAddress((void**)&w2, g_w2);

    dim3 wgrid(EMB / 32, EMB / 32, 4);
    dim3 wblk(32, 8);
    dim3 gq(EMB / TN, M_TOT / TM, 3);    // QKV fused
    dim3 go(EMB / TN, M_TOT / TM, 1);    // O

    adapt_kernel<<<1, 32>>>(xi, ew1, eb1, lng, lnb, ew2, eb2, gate);
    half_kernel<<<nX / 256, 256>>>(query, xh, nX);
    wsplit2_all<<<wgrid, wblk>>>(Wq, Wk, Wv, Wo, w2);
    gemm_mma<<<gq, 256, GEMM_SMEM>>>(xh, w2, bq, bk, bv, bo, out, 0);
    flash_tc<<<dim3(SEQ / 128, NH, BATCH), 256, FLASH_SMEM>>>();
    gemm_mma<<<go, 256, GEMM_SMEM>>>(ah, w2, bq, bk, bv, bo, out, 3);
}

// round 13
// speedup vs baseline: 1.9667x; 1.0522x over previous
#include <cuda_runtime.h>
#include <cuda_fp16.h>
#include <cstdint>
#include <math.h>

// Problem constants
constexpr int BATCH = 2;
constexpr int SEQ   = 2048;
constexpr int EMB   = 1024;
constexpr int NH    = 16;
constexpr int HD    = 64;
constexpr int HD2   = 32;
constexpr int M_TOT = BATCH * SEQ;   // 4096

// GEMM tiling (mma.sync fp16; A = x (K=1024), B = [Whi | Wlo] (K2=2048)).
// K-chunks processed in pairs (p, p+16) sharing the same A chunk.
constexpr int TM  = 128;
constexpr int TN  = 128;
constexpr int K2  = 2 * EMB;          // 2048
constexpr int KC  = 64;               // fp16 per chunk = 128 B rows
constexpr int NPAIR = 16;             // A chunks
constexpr uint32_t GA_ST = 16384;     // A stage stride (16 KB)
constexpr uint32_t GB_OFF = 32768;    // B region base
constexpr uint32_t GB_ST = 32768;     // B pair-stage stride (2 tiles)
constexpr uint32_t GEMM_SMEM = 98304; // A 2x16K + B 2x32K

// Flash smem layout (bytes)
constexpr uint32_t FQ   = 0;           // 16 KB q fp16 (reused for O-reduce)
constexpr uint32_t FKV  = 16384;       // 2 stages x 16 KB (K 8K, V 8K)
constexpr uint32_t FSTG = 16384;
constexpr uint32_t FLSM = 49152;       // 512 B for l
constexpr uint32_t FLASH_SMEM = 49152 + 512;

// ---------------------------------------------------------------------------
// Scratch (device globals -- no runtime allocation allowed)
// ---------------------------------------------------------------------------
__device__ float g_adapt[BATCH * EMB];

__device__ __half g_xh[(size_t)M_TOT * EMB];        // x rounded to fp16
__device__ __half g_ah[(size_t)M_TOT * EMB];        // attention out fp16
__device__ __half g_w2[4][(size_t)EMB * K2];        // transposed [n][whi | wlo]

__device__ __half g_qh[(size_t)BATCH * NH * SEQ * HD];  // [bh][s][d]
__device__ __half g_kh[(size_t)BATCH * NH * SEQ * HD];
__device__ __half g_vth[(size_t)BATCH * NH * HD * SEQ]; // [bh][d][s]

// ---------------------------------------------------------------------------
// Helpers
// ---------------------------------------------------------------------------
__device__ __forceinline__ uint32_t smem_u32(const void* p) {
    uint32_t a;
    asm("{ .reg .u64 t; cvta.to.shared.u64 t, %1; cvt.u32.u64 %0, t; }" : "=r"(a) : "l"(p));
    return a;
}
#define SWZ128(off) ((off) ^ (((off) >> 3) & 0x70))

__device__ __forceinline__ void cp16(uint32_t d, const void* g) {
    asm volatile("cp.async.cg.shared.global [%0], [%1], 16;" :: "r"(d), "l"(g));
}
__device__ __forceinline__ void ldm4(uint32_t* f, uint32_t addr) {
    asm volatile("ldmatrix.sync.aligned.m8n8.x4.shared.b16 {%0,%1,%2,%3}, [%4];"
        : "=r"(f[0]), "=r"(f[1]), "=r"(f[2]), "=r"(f[3]) : "r"(addr));
}
__device__ __forceinline__ void mma16816(float* c, const uint32_t* a, uint32_t b0, uint32_t b1) {
    asm volatile("mma.sync.aligned.m16n8k16.row.col.f32.f16.f16.f32 "
        "{%0,%1,%2,%3}, {%4,%5,%6,%7}, {%8,%9}, {%0,%1,%2,%3};"
        : "+f"(c[0]), "+f"(c[1]), "+f"(c[2]), "+f"(c[3])
        : "r"(a[0]), "r"(a[1]), "r"(a[2]), "r"(a[3]), "r"(b0), "r"(b1));
}
__device__ __forceinline__ float fast_ex2(float x) {
    float y; asm("ex2.approx.f32 %0, %1;" : "=f"(y) : "f"(x)); return y;
}
__device__ __forceinline__ uint32_t pack_h2(float a, float b) {
    __half2 t = __floats2half2_rn(a, b);
    uint32_t r;
    memcpy(&r, &t, 4);
    return r;
}

// ---------------------------------------------------------------------------
// Kernel: adapt
// ---------------------------------------------------------------------------
__global__ void adapt_kernel(const float* __restrict__ xi,
                             const float* __restrict__ ew1, const float* __restrict__ eb1,
                             const float* __restrict__ lng, const float* __restrict__ lnb,
                             const float* __restrict__ ew2, const float* __restrict__ eb2,
                             const float* __restrict__ gate)
{
    int b = threadIdx.x;
    if (b >= BATCH) return;
    float x[HD2];
    float xv = xi[b];
    float mu = 0.f;
#pragma unroll
    for (int i = 0; i < HD2; ++i) { x[i] = xv * ew1[i] + eb1[i]; mu += x[i]; }
    mu *= (1.0f / HD2);
    float var = 0.f;
#pragma unroll
    for (int i = 0; i < HD2; ++i) { float d = x[i] - mu; var += d * d; }
    var *= (1.0f / HD2);
    float rs = rsqrtf(var + 1e-5f);
#pragma unroll
    for (int i = 0; i < HD2; ++i) {
        float xn = (x[i] - mu) * rs * lng[i] + lnb[i];
        x[i] = 0.5f * xn * (1.f + erff(xn * 0.70710678118654752f));
    }
    float sg[NH];
#pragma unroll
    for (int h = 0; h < NH; ++h) sg[h] = 1.f / (1.f + expf(-gate[h]));
    for (int d = 0; d < HD; ++d) {
        float xe = eb2[d];
#pragma unroll
        for (int i = 0; i < HD2; ++i) xe += x[i] * ew2[i * HD + d];
#pragma unroll
        for (int h = 0; h < NH; ++h)
            g_adapt[b * EMB + h * HD + d] = 1.f + sg[h] * xe;
    }
}

// ---------------------------------------------------------------------------
// Kernel: fp32 -> fp16 (x4 vectorized)
// ---------------------------------------------------------------------------
__global__ void __launch_bounds__(256)
half_kernel(const float4* __restrict__ in, uint2* __restrict__ out, int n4)
{
    int i = blockIdx.x * 256 + threadIdx.x;
    if (i < n4) {
        float4 v = in[i];
        uint2 r;
        r.x = pack_h2(v.x, v.y);
        r.y = pack_h2(v.z, v.w);
        out[i] = r;
    }
}

// ---------------------------------------------------------------------------
// Kernel: all four W[K,N] fp32 -> transposed fp16 [N, 2048] = [hi | lo]
// ---------------------------------------------------------------------------
__global__ void __launch_bounds__(256)
wsplit2_all(const float* __restrict__ Wq, const float* __restrict__ Wk,
            const float* __restrict__ Wv, const float* __restrict__ Wo,
            __half* __restrict__ w2base)
{
    const float* W = (blockIdx.z == 0) ? Wq : (blockIdx.z == 1) ? Wk
                   : (blockIdx.z == 2) ? Wv : Wo;
    __half* out2 = w2base + (size_t)blockIdx.z * EMB * K2;

    __shared__ float t[32][33];
    int n0 = blockIdx.x * 32, k0 = blockIdx.y * 32;
    int tx = threadIdx.x, ty = threadIdx.y;   // (32, 8)
#pragma unroll
    for (int i = 0; i < 32; i += 8)
        t[ty + i][tx] = W[(size_t)(k0 + ty + i) * EMB + n0 + tx];
    __syncthreads();
#pragma unroll
    for (int i = 0; i < 32; i += 8) {
        float x = t[tx][ty + i];              // k=k0+tx, n=n0+ty+i
        __half h = __float2half_rn(x);
        __half l = __float2half_rn(x - __half2float(h));
        size_t base = (size_t)(n0 + ty + i) * K2 + k0 + tx;
        out2[base]       = h;
        out2[base + EMB] = l;
    }
}

// ---------------------------------------------------------------------------
// Kernel: mma.sync fp16 GEMM with paired K-chunks.
// C[M,N] = A[M,1024] * ([Whi|Wlo])[N,2048]^T + bias.
// Pair p covers B chunks p (Whi part) and p+16 (Wlo part); both share A
// chunk p: A is loaded to smem once and its fragments reused for both.
// mode = mode_base + blockIdx.z (0 Q / 1 K / 2 V / 3 O).
// ---------------------------------------------------------------------------
__global__ void __launch_bounds__(256)
gemm_mma(const __half* __restrict__ Ah, const __half* __restrict__ w2base,
         const float* __restrict__ bq, const float* __restrict__ bk,
         const float* __restrict__ bv, const float* __restrict__ bo,
         float* __restrict__ out, int mode_base)
{
    extern __shared__ __align__(1024) char smem[];
    const uint32_t sb = smem_u32(smem);
    const int tid  = threadIdx.x;
    const int lane = tid & 31;
    const int wid  = tid >> 5;
    const int wm   = wid >> 1;        // 0..3
    const int wn   = wid & 1;         // 0..1
    const int m0 = blockIdx.y * TM;
    const int n0 = blockIdx.x * TN;
    const int mode = mode_base + blockIdx.z;

    const float* bias = (mode == 0) ? bq : (mode == 1) ? bk : (mode == 2) ? bv : bo;
    const __half* Ab = Ah + (size_t)m0 * EMB;
    const __half* Bb = w2base + (size_t)mode * EMB * K2 + (size_t)n0 * K2;

    float c[2][8][4];
#pragma unroll
    for (int a = 0; a < 2; ++a)
#pragma unroll
        for (int b = 0; b < 8; ++b)
#pragma unroll
            for (int d = 0; d < 4; ++d) c[a][b][d] = 0.f;

    // Prefetch pair p: A chunk p (16 KB) + B chunks p, p+16 (2 x 16 KB)
#define PREPAIR(p)                                                                     \
    do {                                                                               \
        uint32_t sta = sb + ((p) & 1) * GA_ST;                                         \
        uint32_t stb = sb + GB_OFF + ((p) & 1) * GB_ST;                                \
        _Pragma("unroll")                                                              \
        for (int i = 0; i < 4; ++i) {                                                  \
            int idx = tid + i * 256;                                                   \
            int r = idx >> 3, u = idx & 7;                                             \
            uint32_t sw = SWZ128(r * 128 + u * 16);                                    \
            cp16(sta + sw, Ab + (size_t)r * EMB + (p) * KC + u * 8);                   \
            cp16(stb + sw, Bb + (size_t)r * K2 + (p) * KC + u * 8);                    \
            cp16(stb + 16384 + sw, Bb + (size_t)r * K2 + EMB + (p) * KC + u * 8);      \
        }                                                                              \
        asm volatile("cp.async.commit_group;");                                        \
    } while (0)

    PREPAIR(0);
    asm volatile("cp.async.wait_group 0;");
    __syncthreads();

    for (int p = 0; p < NPAIR; ++p) {
        if (p + 1 < NPAIR) PREPAIR(p + 1);

        const uint32_t sta = sb + (p & 1) * GA_ST;
        const uint32_t stb = sb + GB_OFF + (p & 1) * GB_ST;
        const int rr = lane & 15;

#pragma unroll
        for (int ks = 0; ks < 4; ++ks) {
            const int uu = 2 * ks + (lane >> 4);
            uint32_t afr[2][4];
#pragma unroll
            for (int mt = 0; mt < 2; ++mt)
                ldm4(afr[mt], sta + SWZ128((wm * 32 + mt * 16 + rr) * 128 + uu * 16));
#pragma unroll
            for (int half = 0; half < 2; ++half) {
                uint32_t bfr[4][4];
#pragma unroll
                for (int ng = 0; ng < 4; ++ng)
                    ldm4(bfr[ng], stb + half * 16384 +
                                  SWZ128((wn * 64 + ng * 16 + rr) * 128 + uu * 16));
#pragma unroll
                for (int mt = 0; mt < 2; ++mt)
#pragma unroll
                    for (int ng = 0; ng < 4; ++ng) {
                        mma16816(c[mt][ng * 2],     afr[mt], bfr[ng][0], bfr[ng][2]);
                        mma16816(c[mt][ng * 2 + 1], afr[mt], bfr[ng][1], bfr[ng][3]);
                    }
            }
        }

        if (p + 1 < NPAIR) {
            asm volatile("cp.async.wait_group 0;");
            __syncthreads();
        }
    }
#undef PREPAIR
    __syncthreads();

    // ---------------- epilogues ----------------
    if (mode == 2) {
        // V: stage transposed fp16 in smem, then coalesced store to [bh][d][s]
#pragma unroll
        for (int mt = 0; mt < 2; ++mt) {
            int mrow = wm * 32 + mt * 16 + (lane >> 2);
#pragma unroll
            for (int nt = 0; nt < 8; ++nt) {
                int nl = wn * 64 + nt * 8 + (lane & 3) * 2;
                float b0 = bias[n0 + nl], b1 = bias[n0 + nl + 1];
#pragma unroll
                for (int half = 0; half < 2; ++half) {
                    int ml = mrow + half * 8;
                    *(__half*)(smem + nl * 256 + ml * 2) =
                        __float2half_rn(c[mt][nt][half * 2] + b0);
                    *(__half*)(smem + (nl + 1) * 256 + ml * 2) =
                        __float2half_rn(c[mt][nt][half * 2 + 1] + b1);
                }
            }
        }
        __syncthreads();
        int bq2 = m0 >> 11, sq = m0 & 2047;
        int hbase = n0 >> 6;
        for (int cidx = tid; cidx < 2048; cidx += 256) {
            int nn = cidx >> 4, mc = cidx & 15;
            uint4 hv = *(uint4*)(smem + nn * 256 + mc * 16);
            size_t o = (((size_t)(bq2 * NH + hbase + (nn >> 6)) * HD + (nn & 63)) * SEQ
                        + sq + mc * 8);
            *(uint4*)&g_vth[o] = hv;
        }
        return;
    }

#pragma unroll
    for (int mt = 0; mt < 2; ++mt) {
        int row0 = wm * 32 + mt * 16 + (lane >> 2);
#pragma unroll
        for (int nt = 0; nt < 8; ++nt) {
            int n = n0 + wn * 64 + nt * 8 + (lane & 3) * 2;
            float b0 = bias[n], b1 = bias[n + 1];
#pragma unroll
            for (int half = 0; half < 2; ++half) {
                int m = m0 + row0 + half * 8;
                int b = m >> 11, s = m & 2047;
                float v0 = c[mt][nt][half * 2] + b0;
                float v1 = c[mt][nt][half * 2 + 1] + b1;
                if (mode == 3) {
                    *(float2*)&out[(size_t)m * EMB + n] = make_float2(v0, v1);
                } else {
                    const float sc0 = (mode == 0) ? 0.18033688f : 1.0f;  // 1.442695/8
                    v0 *= g_adapt[b * EMB + n] * sc0;
                    v1 *= g_adapt[b * EMB + n + 1] * sc0;
                    int h = n >> 6, d = n & 63;
                    size_t o = ((size_t)(b * NH + h) * SEQ + s) * HD + d;
                    uint32_t hp = pack_h2(v0, v1);
                    if (mode == 0) *(uint32_t*)&g_qh[o] = hp;
                    else           *(uint32_t*)&g_kh[o] = hp;
                }
            }
        }
    }
}

// ---------------------------------------------------------------------------
// Kernel: tensor-core flash attention, fp16 single-term, P in registers,
// Q fragments hoisted out of the K-loop.
// ---------------------------------------------------------------------------
__global__ void __launch_bounds__(256)
flash_tc()
{
    extern __shared__ __align__(1024) char smem[];
    const uint32_t sb = smem_u32(smem);
    const int tid = threadIdx.x, lane = tid & 31, wid = tid >> 5;
    const int wm = wid >> 1, wn = wid & 1;
    const int s0 = blockIdx.x * 128;
    const int h  = blockIdx.y, b = blockIdx.z;
    const int bh = b * NH + h;
    const int rr = lane & 15;

    if (tid < 128) *(float*)(smem + FLSM + tid * 4) = 0.f;

    const __half* qh  = g_qh + ((size_t)bh * SEQ + s0) * HD;
    const __half* kh  = g_kh + (size_t)bh * SEQ * HD;
    const __half* vth = g_vth + (size_t)bh * HD * SEQ;

    // Q tile + first KV stage
#pragma unroll
    for (int i = 0; i < 4; ++i) {
        int idx = tid + i * 256;       // 0..1023
        int r = idx >> 3, u = idx & 7;
        cp16(sb + FQ + SWZ128(r * 128 + u * 16), qh + r * HD + u * 8);
    }
    asm volatile("cp.async.commit_group;");

#define KVPRE(kb)                                                                       \
    do {                                                                                \
        uint32_t st = sb + FKV + ((kb) & 1) * FSTG;                                     \
        _Pragma("unroll")                                                               \
        for (int i = 0; i < 2; ++i) {                                                   \
            int idx = tid + i * 256;     /* 0..511 */                                   \
            int r = idx >> 3, u = idx & 7;                                              \
            uint32_t sw = SWZ128(r * 128 + u * 16);                                     \
            cp16(st + sw,        kh + ((size_t)(kb) * 64 + r) * HD + u * 8);            \
            cp16(st + 8192 + sw, vth + (size_t)r * SEQ + (kb) * 64 + u * 8);            \
        }                                                                               \
        asm volatile("cp.async.commit_group;");                                         \
    } while (0)

    KVPRE(0);
    asm volatile("cp.async.wait_group 0;");
    __syncthreads();

    // hoist Q fragments (loop-invariant): qf[ks][mt][4]
    uint32_t qf[4][2][4];
#pragma unroll
    for (int ks = 0; ks < 4; ++ks) {
        const int uu = 2 * ks + (lane >> 4);
#pragma unroll
        for (int mt = 0; mt < 2; ++mt)
            ldm4(qf[ks][mt], sb + FQ + SWZ128((wm * 32 + mt * 16 + rr) * 128 + uu * 16));
    }

    float oc[2][8][4];
#pragma unroll
    for (int a = 0; a < 2; ++a)
#pragma unroll
        for (int f = 0; f < 8; ++f)
#pragma unroll
            for (int d = 0; d < 4; ++d) oc[a][f][d] = 0.f;
    float l_part[4] = {0.f, 0.f, 0.f, 0.f};

#pragma unroll 1
    for (int kb = 0; kb < SEQ / 64; ++kb) {
        if (kb + 1 < SEQ / 64) KVPRE(kb + 1);

        const uint32_t stg = sb + FKV + (kb & 1) * FSTG;

        // ---- S = Q K^T (fp16 single term) ----
        float sc[2][4][4];
#pragma unroll
        for (int a = 0; a < 2; ++a)
#pragma unroll
            for (int f = 0; f < 4; ++f)
#pragma unroll
                for (int d = 0; d < 4; ++d) sc[a][f][d] = 0.f;

#pragma unroll
        for (int ks = 0; ks < 4; ++ks) {
            const int uu = 2 * ks + (lane >> 4);
            uint32_t bH[2][4];
#pragma unroll
            for (int ng = 0; ng < 2; ++ng)
                ldm4(bH[ng], stg + SWZ128((wn * 32 + ng * 16 + rr) * 128 + uu * 16));
#pragma unroll
            for (int mt = 0; mt < 2; ++mt)
#pragma unroll
                for (int ng = 0; ng < 2; ++ng) {
                    mma16816(sc[mt][ng * 2],     qf[ks][mt], bH[ng][0], bH[ng][2]);
                    mma16816(sc[mt][ng * 2 + 1], qf[ks][mt], bH[ng][1], bH[ng][3]);
                }
        }

        // ---- p = 2^s; pack fp16 A-fragments in registers ----
        uint32_t pA[2][4], pB[2][4];
#pragma unroll
        for (int mt = 0; mt < 2; ++mt)
#pragma unroll
            for (int nf = 0; nf < 4; ++nf) {
                float p0 = fast_ex2(sc[mt][nf][0]);
                float p1 = fast_ex2(sc[mt][nf][1]);
                float p2 = fast_ex2(sc[mt][nf][2]);
                float p3 = fast_ex2(sc[mt][nf][3]);
                l_part[mt * 2 + 0] += p0 + p1;
                l_part[mt * 2 + 1] += p2 + p3;
                pA[mt][nf] = pack_h2(p0, p1);
                pB[mt][nf] = pack_h2(p2, p3);
            }

        // ---- O_partial += P V over this warp's 32 keys, all 64 d ----
#pragma unroll
        for (int ksp = 0; ksp < 2; ++ksp) {
            const int uu = 2 * (wn * 2 + ksp) + (lane >> 4);
            uint32_t bV[4][4];
#pragma unroll
            for (int g = 0; g < 4; ++g)
                ldm4(bV[g], stg + 8192 + SWZ128((g * 16 + rr) * 128 + uu * 16));
#pragma unroll
            for (int mt = 0; mt < 2; ++mt) {
                uint32_t aP[4] = {pA[mt][2 * ksp], pB[mt][2 * ksp],
                                  pA[mt][2 * ksp + 1], pB[mt][2 * ksp + 1]};
#pragma unroll
                for (int g = 0; g < 4; ++g) {
                    mma16816(oc[mt][2 * g],     aP, bV[g][0], bV[g][2]);
                    mma16816(oc[mt][2 * g + 1], aP, bV[g][1], bV[g][3]);
                }
            }
        }

        // stage kb fully consumed; wait for kb+1 data and make write-safe
        if (kb + 1 < SEQ / 64) {
            asm volatile("cp.async.wait_group 0;");
            __syncthreads();
        }
    }
#undef KVPRE

    // ---- reduce l across the 4 lanes of each row-group ----
#pragma unroll
    for (int j = 0; j < 4; ++j) {
        l_part[j] += __shfl_xor_sync(0xFFFFFFFF, l_part[j], 1);
        l_part[j] += __shfl_xor_sync(0xFFFFFFFF, l_part[j], 2);
    }
    if ((lane & 3) == 0) {
#pragma unroll
        for (int mt = 0; mt < 2; ++mt)
#pragma unroll
            for (int half = 0; half < 2; ++half) {
                int r = wm * 32 + mt * 16 + (lane >> 2) + half * 8;
                atomicAdd((float*)(smem + FLSM + r * 4), l_part[mt * 2 + half]);
            }
    }
    __syncthreads();   // all PV done; Q area now dead -> O reduce buffer (32 KB)

    if (wn == 1) {
#pragma unroll
        for (int mt = 0; mt < 2; ++mt) {
            int row = wm * 32 + mt * 16 + (lane >> 2);
#pragma unroll
            for (int nf = 0; nf < 8; ++nf) {
                int col = nf * 8 + (lane & 3) * 2;
                *(float2*)(smem + (row * 64 + col) * 4) =
                    make_float2(oc[mt][nf][0], oc[mt][nf][1]);
                *(float2*)(smem + ((row + 8) * 64 + col) * 4) =
                    make_float2(oc[mt][nf][2], oc[mt][nf][3]);
            }
        }
    }
    __syncthreads();

    if (wn == 0) {
#pragma unroll
        for (int mt = 0; mt < 2; ++mt)
#pragma unroll
            for (int half = 0; half < 2; ++half) {
                int r = wm * 32 + mt * 16 + (lane >> 2) + half * 8;
                float inv = 1.f / *(float*)(smem + FLSM + r * 4);
                size_t mrow = (size_t)(b * SEQ + s0 + r) * EMB;
#pragma unroll
                for (int nf = 0; nf < 8; ++nf) {
                    int col = nf * 8 + (lane & 3) * 2;
                    float2 part = *(float2*)(smem + (r * 64 + col) * 4);
                    float v0 = (oc[mt][nf][half * 2]     + part.x) * inv;
                    float v1 = (oc[mt][nf][half * 2 + 1] + part.y) * inv;
                    *(uint32_t*)&g_ah[mrow + h * HD + col] = pack_h2(v0, v1);
                }
            }
    }
}

// ---------------------------------------------------------------------------
// Launch
// ---------------------------------------------------------------------------
extern "C" void kernel_launch(void* const* d_in, const int* in_sizes, int n_in,
                              void* d_out, int out_size)
{
    const float* query = (const float*)d_in[0];
    const float* xi    = (const float*)d_in[1];
    const float* Wq    = (const float*)d_in[2];
    const float* bq    = (const float*)d_in[3];
    const float* Wk    = (const float*)d_in[4];
    const float* bk    = (const float*)d_in[5];
    const float* Wv    = (const float*)d_in[6];
    const float* bv    = (const float*)d_in[7];
    const float* Wo    = (const float*)d_in[8];
    const float* bo    = (const float*)d_in[9];
    const float* ew1   = (const float*)d_in[10];
    const float* eb1   = (const float*)d_in[11];
    const float* lng   = (const float*)d_in[12];
    const float* lnb   = (const float*)d_in[13];
    const float* ew2   = (const float*)d_in[14];
    const float* eb2   = (const float*)d_in[15];
    const float* gate  = (const float*)d_in[16];
    float* out = (float*)d_out;

    // Idempotent, capture-safe, no static guard (harness rule).
    cudaFuncSetAttribute(gemm_mma, cudaFuncAttributeMaxDynamicSharedMemorySize, GEMM_SMEM);
    cudaFuncSetAttribute(flash_tc, cudaFuncAttributeMaxDynamicSharedMemorySize, FLASH_SMEM);

    int nX = M_TOT * EMB;
    __half *xh, *ah, *w2;
    cudaGetSymbolAddress((void**)&xh, g_xh);
    cudaGetSymbolAddress((void**)&ah, g_ah);
    cudaGetSymbolAddress((void**)&w2, g_w2);

    dim3 wgrid(EMB / 32, EMB / 32, 4);
    dim3 wblk(32, 8);
    dim3 gq(EMB / TN, M_TOT / TM, 3);    // QKV fused
    dim3 go(EMB / TN, M_TOT / TM, 1);    // O

    adapt_kernel<<<1, 32>>>(xi, ew1, eb1, lng, lnb, ew2, eb2, gate);
    half_kernel<<<nX / 1024, 256>>>((const float4*)query, (uint2*)xh, nX / 4);
    wsplit2_all<<<wgrid, wblk>>>(Wq, Wk, Wv, Wo, w2);
    gemm_mma<<<gq, 256, GEMM_SMEM>>>(xh, w2, bq, bk, bv, bo, out, 0);
    flash_tc<<<dim3(SEQ / 128, NH, BATCH), 256, FLASH_SMEM>>>();
    gemm_mma<<<go, 256, GEMM_SMEM>>>(ah, w2, bq, bk, bv, bo, out, 3);
}

// round 14
// speedup vs baseline: 2.0191x; 1.0266x over previous
#include <cuda_runtime.h>
#include <cuda_fp16.h>
#include <cstdint>
#include <math.h>

// Problem constants
constexpr int BATCH = 2;
constexpr int SEQ   = 2048;
constexpr int EMB   = 1024;
constexpr int NH    = 16;
constexpr int HD    = 64;
constexpr int HD2   = 32;
constexpr int M_TOT = BATCH * SEQ;   // 4096

// GEMM tiling (mma.sync fp16; A = x (K=1024), B = [Whi | Wlo] (K2=2048)).
// K-chunks processed in pairs (p, p+16) sharing the same A chunk.
constexpr int TM  = 128;
constexpr int TN  = 128;
constexpr int K2  = 2 * EMB;          // 2048
constexpr int KC  = 64;               // fp16 per chunk = 128 B rows
constexpr int NPAIR = 16;             // A chunks
constexpr uint32_t GA_ST = 16384;     // A stage stride (16 KB)
constexpr uint32_t GB_OFF = 32768;    // B region base
constexpr uint32_t GB_ST = 32768;     // B pair-stage stride (2 tiles)
constexpr uint32_t GEMM_SMEM = 98304; // A 2x16K + B 2x32K

// Flash smem layout (bytes)
constexpr uint32_t FQ   = 0;           // 16 KB q fp16 (reused for O-reduce)
constexpr uint32_t FKV  = 16384;       // 2 stages x 16 KB (K 8K, V 8K)
constexpr uint32_t FSTG = 16384;
constexpr uint32_t FLSM = 49152;       // 512 B for l
constexpr uint32_t FLASH_SMEM = 49152 + 512;

// ---------------------------------------------------------------------------
// Scratch (device globals -- no runtime allocation allowed)
// ---------------------------------------------------------------------------
__device__ float g_adapt[BATCH * EMB];

__device__ __half g_xh[(size_t)M_TOT * EMB];        // x rounded to fp16
__device__ __half g_ah[(size_t)M_TOT * EMB];        // attention out fp16
__device__ __half g_w2[4][(size_t)EMB * K2];        // transposed [n][whi | wlo]

__device__ __half g_qh[(size_t)BATCH * NH * SEQ * HD];  // [bh][s][d]
__device__ __half g_kh[(size_t)BATCH * NH * SEQ * HD];
__device__ __half g_vth[(size_t)BATCH * NH * HD * SEQ]; // [bh][d][s]

// ---------------------------------------------------------------------------
// Helpers
// ---------------------------------------------------------------------------
__device__ __forceinline__ uint32_t smem_u32(const void* p) {
    uint32_t a;
    asm("{ .reg .u64 t; cvta.to.shared.u64 t, %1; cvt.u32.u64 %0, t; }" : "=r"(a) : "l"(p));
    return a;
}
#define SWZ128(off) ((off) ^ (((off) >> 3) & 0x70))

__device__ __forceinline__ void cp16(uint32_t d, const void* g) {
    asm volatile("cp.async.cg.shared.global [%0], [%1], 16;" :: "r"(d), "l"(g));
}
__device__ __forceinline__ void ldm4(uint32_t* f, uint32_t addr) {
    asm volatile("ldmatrix.sync.aligned.m8n8.x4.shared.b16 {%0,%1,%2,%3}, [%4];"
        : "=r"(f[0]), "=r"(f[1]), "=r"(f[2]), "=r"(f[3]) : "r"(addr));
}
__device__ __forceinline__ void mma16816(float* c, const uint32_t* a, uint32_t b0, uint32_t b1) {
    asm volatile("mma.sync.aligned.m16n8k16.row.col.f32.f16.f16.f32 "
        "{%0,%1,%2,%3}, {%4,%5,%6,%7}, {%8,%9}, {%0,%1,%2,%3};"
        : "+f"(c[0]), "+f"(c[1]), "+f"(c[2]), "+f"(c[3])
        : "r"(a[0]), "r"(a[1]), "r"(a[2]), "r"(a[3]), "r"(b0), "r"(b1));
}
__device__ __forceinline__ float fast_ex2(float x) {
    float y; asm("ex2.approx.f32 %0, %1;" : "=f"(y) : "f"(x)); return y;
}
__device__ __forceinline__ uint32_t pack_h2(float a, float b) {
    __half2 t = __floats2half2_rn(a, b);
    uint32_t r;
    memcpy(&r, &t, 4);
    return r;
}

// ---------------------------------------------------------------------------
// Kernel: adapt
// ---------------------------------------------------------------------------
__global__ void adapt_kernel(const float* __restrict__ xi,
                             const float* __restrict__ ew1, const float* __restrict__ eb1,
                             const float* __restrict__ lng, const float* __restrict__ lnb,
                             const float* __restrict__ ew2, const float* __restrict__ eb2,
                             const float* __restrict__ gate)
{
    int b = threadIdx.x;
    if (b >= BATCH) return;
    float x[HD2];
    float xv = xi[b];
    float mu = 0.f;
#pragma unroll
    for (int i = 0; i < HD2; ++i) { x[i] = xv * ew1[i] + eb1[i]; mu += x[i]; }
    mu *= (1.0f / HD2);
    float var = 0.f;
#pragma unroll
    for (int i = 0; i < HD2; ++i) { float d = x[i] - mu; var += d * d; }
    var *= (1.0f / HD2);
    float rs = rsqrtf(var + 1e-5f);
#pragma unroll
    for (int i = 0; i < HD2; ++i) {
        float xn = (x[i] - mu) * rs * lng[i] + lnb[i];
        x[i] = 0.5f * xn * (1.f + erff(xn * 0.70710678118654752f));
    }
    float sg[NH];
#pragma unroll
    for (int h = 0; h < NH; ++h) sg[h] = 1.f / (1.f + expf(-gate[h]));
    for (int d = 0; d < HD; ++d) {
        float xe = eb2[d];
#pragma unroll
        for (int i = 0; i < HD2; ++i) xe += x[i] * ew2[i * HD + d];
#pragma unroll
        for (int h = 0; h < NH; ++h)
            g_adapt[b * EMB + h * HD + d] = 1.f + sg[h] * xe;
    }
}

// ---------------------------------------------------------------------------
// Kernel: fp32 -> fp16 (x4 vectorized)
// ---------------------------------------------------------------------------
__global__ void __launch_bounds__(256)
half_kernel(const float4* __restrict__ in, uint2* __restrict__ out, int n4)
{
    int i = blockIdx.x * 256 + threadIdx.x;
    if (i < n4) {
        float4 v = in[i];
        uint2 r;
        r.x = pack_h2(v.x, v.y);
        r.y = pack_h2(v.z, v.w);
        out[i] = r;
    }
}

// ---------------------------------------------------------------------------
// Kernel: all four W[K,N] fp32 -> transposed fp16 [N, 2048] = [hi | lo]
// ---------------------------------------------------------------------------
__global__ void __launch_bounds__(256)
wsplit2_all(const float* __restrict__ Wq, const float* __restrict__ Wk,
            const float* __restrict__ Wv, const float* __restrict__ Wo,
            __half* __restrict__ w2base)
{
    const float* W = (blockIdx.z == 0) ? Wq : (blockIdx.z == 1) ? Wk
                   : (blockIdx.z == 2) ? Wv : Wo;
    __half* out2 = w2base + (size_t)blockIdx.z * EMB * K2;

    __shared__ float t[32][33];
    int n0 = blockIdx.x * 32, k0 = blockIdx.y * 32;
    int tx = threadIdx.x, ty = threadIdx.y;   // (32, 8)
#pragma unroll
    for (int i = 0; i < 32; i += 8)
        t[ty + i][tx] = W[(size_t)(k0 + ty + i) * EMB + n0 + tx];
    __syncthreads();
#pragma unroll
    for (int i = 0; i < 32; i += 8) {
        float x = t[tx][ty + i];              // k=k0+tx, n=n0+ty+i
        __half h = __float2half_rn(x);
        __half l = __float2half_rn(x - __half2float(h));
        size_t base = (size_t)(n0 + ty + i) * K2 + k0 + tx;
        out2[base]       = h;
        out2[base + EMB] = l;
    }
}

// ---------------------------------------------------------------------------
// Kernel: mma.sync fp16 GEMM with paired K-chunks (unchanged from R13).
// ---------------------------------------------------------------------------
__global__ void __launch_bounds__(256)
gemm_mma(const __half* __restrict__ Ah, const __half* __restrict__ w2base,
         const float* __restrict__ bq, const float* __restrict__ bk,
         const float* __restrict__ bv, const float* __restrict__ bo,
         float* __restrict__ out, int mode_base)
{
    extern __shared__ __align__(1024) char smem[];
    const uint32_t sb = smem_u32(smem);
    const int tid  = threadIdx.x;
    const int lane = tid & 31;
    const int wid  = tid >> 5;
    const int wm   = wid >> 1;        // 0..3
    const int wn   = wid & 1;         // 0..1
    const int m0 = blockIdx.y * TM;
    const int n0 = blockIdx.x * TN;
    const int mode = mode_base + blockIdx.z;

    const float* bias = (mode == 0) ? bq : (mode == 1) ? bk : (mode == 2) ? bv : bo;
    const __half* Ab = Ah + (size_t)m0 * EMB;
    const __half* Bb = w2base + (size_t)mode * EMB * K2 + (size_t)n0 * K2;

    float c[2][8][4];
#pragma unroll
    for (int a = 0; a < 2; ++a)
#pragma unroll
        for (int b = 0; b < 8; ++b)
#pragma unroll
            for (int d = 0; d < 4; ++d) c[a][b][d] = 0.f;

#define PREPAIR(p)                                                                     \
    do {                                                                               \
        uint32_t sta = sb + ((p) & 1) * GA_ST;                                         \
        uint32_t stb = sb + GB_OFF + ((p) & 1) * GB_ST;                                \
        _Pragma("unroll")                                                              \
        for (int i = 0; i < 4; ++i) {                                                  \
            int idx = tid + i * 256;                                                   \
            int r = idx >> 3, u = idx & 7;                                             \
            uint32_t sw = SWZ128(r * 128 + u * 16);                                    \
            cp16(sta + sw, Ab + (size_t)r * EMB + (p) * KC + u * 8);                   \
            cp16(stb + sw, Bb + (size_t)r * K2 + (p) * KC + u * 8);                    \
            cp16(stb + 16384 + sw, Bb + (size_t)r * K2 + EMB + (p) * KC + u * 8);      \
        }                                                                              \
        asm volatile("cp.async.commit_group;");                                        \
    } while (0)

    PREPAIR(0);
    asm volatile("cp.async.wait_group 0;");
    __syncthreads();

    for (int p = 0; p < NPAIR; ++p) {
        if (p + 1 < NPAIR) PREPAIR(p + 1);

        const uint32_t sta = sb + (p & 1) * GA_ST;
        const uint32_t stb = sb + GB_OFF + (p & 1) * GB_ST;
        const int rr = lane & 15;

#pragma unroll
        for (int ks = 0; ks < 4; ++ks) {
            const int uu = 2 * ks + (lane >> 4);
            uint32_t afr[2][4];
#pragma unroll
            for (int mt = 0; mt < 2; ++mt)
                ldm4(afr[mt], sta + SWZ128((wm * 32 + mt * 16 + rr) * 128 + uu * 16));
#pragma unroll
            for (int half = 0; half < 2; ++half) {
                uint32_t bfr[4][4];
#pragma unroll
                for (int ng = 0; ng < 4; ++ng)
                    ldm4(bfr[ng], stb + half * 16384 +
                                  SWZ128((wn * 64 + ng * 16 + rr) * 128 + uu * 16));
#pragma unroll
                for (int mt = 0; mt < 2; ++mt)
#pragma unroll
                    for (int ng = 0; ng < 4; ++ng) {
                        mma16816(c[mt][ng * 2],     afr[mt], bfr[ng][0], bfr[ng][2]);
                        mma16816(c[mt][ng * 2 + 1], afr[mt], bfr[ng][1], bfr[ng][3]);
                    }
            }
        }

        if (p + 1 < NPAIR) {
            asm volatile("cp.async.wait_group 0;");
            __syncthreads();
        }
    }
#undef PREPAIR
    __syncthreads();

    // ---------------- epilogues ----------------
    if (mode == 2) {
        // V: stage transposed fp16 in smem, then coalesced store to [bh][d][s]
#pragma unroll
        for (int mt = 0; mt < 2; ++mt) {
            int mrow = wm * 32 + mt * 16 + (lane >> 2);
#pragma unroll
            for (int nt = 0; nt < 8; ++nt) {
                int nl = wn * 64 + nt * 8 + (lane & 3) * 2;
                float b0 = bias[n0 + nl], b1 = bias[n0 + nl + 1];
#pragma unroll
                for (int half = 0; half < 2; ++half) {
                    int ml = mrow + half * 8;
                    *(__half*)(smem + nl * 256 + ml * 2) =
                        __float2half_rn(c[mt][nt][half * 2] + b0);
                    *(__half*)(smem + (nl + 1) * 256 + ml * 2) =
                        __float2half_rn(c[mt][nt][half * 2 + 1] + b1);
                }
            }
        }
        __syncthreads();
        int bq2 = m0 >> 11, sq = m0 & 2047;
        int hbase = n0 >> 6;
        for (int cidx = tid; cidx < 2048; cidx += 256) {
            int nn = cidx >> 4, mc = cidx & 15;
            uint4 hv = *(uint4*)(smem + nn * 256 + mc * 16);
            size_t o = (((size_t)(bq2 * NH + hbase + (nn >> 6)) * HD + (nn & 63)) * SEQ
                        + sq + mc * 8);
            *(uint4*)&g_vth[o] = hv;
        }
        return;
    }

#pragma unroll
    for (int mt = 0; mt < 2; ++mt) {
        int row0 = wm * 32 + mt * 16 + (lane >> 2);
#pragma unroll
        for (int nt = 0; nt < 8; ++nt) {
            int n = n0 + wn * 64 + nt * 8 + (lane & 3) * 2;
            float b0 = bias[n], b1 = bias[n + 1];
#pragma unroll
            for (int half = 0; half < 2; ++half) {
                int m = m0 + row0 + half * 8;
                int b = m >> 11, s = m & 2047;
                float v0 = c[mt][nt][half * 2] + b0;
                float v1 = c[mt][nt][half * 2 + 1] + b1;
                if (mode == 3) {
                    *(float2*)&out[(size_t)m * EMB + n] = make_float2(v0, v1);
                } else {
                    const float sc0 = (mode == 0) ? 0.18033688f : 1.0f;  // 1.442695/8
                    v0 *= g_adapt[b * EMB + n] * sc0;
                    v1 *= g_adapt[b * EMB + n + 1] * sc0;
                    int h = n >> 6, d = n & 63;
                    size_t o = ((size_t)(b * NH + h) * SEQ + s) * HD + d;
                    uint32_t hp = pack_h2(v0, v1);
                    if (mode == 0) *(uint32_t*)&g_qh[o] = hp;
                    else           *(uint32_t*)&g_kh[o] = hp;
                }
            }
        }
    }
}

// ---------------------------------------------------------------------------
// Kernel: tensor-core flash attention, fp16 single-term, P in registers.
// Forced 2 CTAs/SM (launch_bounds minBlocks=2) so a co-resident CTA fills
// the tensor pipe during this CTA's softmax phase. Q fragments reloaded per
// iteration (not hoisted) to keep regs <= 128.
// ---------------------------------------------------------------------------
__global__ void __launch_bounds__(256, 2)
flash_tc()
{
    extern __shared__ __align__(1024) char smem[];
    const uint32_t sb = smem_u32(smem);
    const int tid = threadIdx.x, lane = tid & 31, wid = tid >> 5;
    const int wm = wid >> 1, wn = wid & 1;
    const int s0 = blockIdx.x * 128;
    const int h  = blockIdx.y, b = blockIdx.z;
    const int bh = b * NH + h;
    const int rr = lane & 15;

    if (tid < 128) *(float*)(smem + FLSM + tid * 4) = 0.f;

    const __half* qh  = g_qh + ((size_t)bh * SEQ + s0) * HD;
    const __half* kh  = g_kh + (size_t)bh * SEQ * HD;
    const __half* vth = g_vth + (size_t)bh * HD * SEQ;

    // Q tile + first KV stage
#pragma unroll
    for (int i = 0; i < 4; ++i) {
        int idx = tid + i * 256;       // 0..1023
        int r = idx >> 3, u = idx & 7;
        cp16(sb + FQ + SWZ128(r * 128 + u * 16), qh + r * HD + u * 8);
    }
    asm volatile("cp.async.commit_group;");

#define KVPRE(kb)                                                                       \
    do {                                                                                \
        uint32_t st = sb + FKV + ((kb) & 1) * FSTG;                                     \
        _Pragma("unroll")                                                               \
        for (int i = 0; i < 2; ++i) {                                                   \
            int idx = tid + i * 256;     /* 0..511 */                                   \
            int r = idx >> 3, u = idx & 7;                                              \
            uint32_t sw = SWZ128(r * 128 + u * 16);                                     \
            cp16(st + sw,        kh + ((size_t)(kb) * 64 + r) * HD + u * 8);            \
            cp16(st + 8192 + sw, vth + (size_t)r * SEQ + (kb) * 64 + u * 8);            \
        }                                                                               \
        asm volatile("cp.async.commit_group;");                                         \
    } while (0)

    KVPRE(0);
    asm volatile("cp.async.wait_group 0;");
    __syncthreads();

    float oc[2][8][4];
#pragma unroll
    for (int a = 0; a < 2; ++a)
#pragma unroll
        for (int f = 0; f < 8; ++f)
#pragma unroll
            for (int d = 0; d < 4; ++d) oc[a][f][d] = 0.f;
    float l_part[4] = {0.f, 0.f, 0.f, 0.f};

#pragma unroll 1
    for (int kb = 0; kb < SEQ / 64; ++kb) {
        if (kb + 1 < SEQ / 64) KVPRE(kb + 1);

        const uint32_t stg = sb + FKV + (kb & 1) * FSTG;

        // ---- S = Q K^T (fp16 single term) ----
        float sc[2][4][4];
#pragma unroll
        for (int a = 0; a < 2; ++a)
#pragma unroll
            for (int f = 0; f < 4; ++f)
#pragma unroll
                for (int d = 0; d < 4; ++d) sc[a][f][d] = 0.f;

#pragma unroll
        for (int ks = 0; ks < 4; ++ks) {
            const int uu = 2 * ks + (lane >> 4);
            uint32_t aH[2][4], bH[2][4];
#pragma unroll
            for (int mt = 0; mt < 2; ++mt)
                ldm4(aH[mt], sb + FQ + SWZ128((wm * 32 + mt * 16 + rr) * 128 + uu * 16));
#pragma unroll
            for (int ng = 0; ng < 2; ++ng)
                ldm4(bH[ng], stg + SWZ128((wn * 32 + ng * 16 + rr) * 128 + uu * 16));
#pragma unroll
            for (int mt = 0; mt < 2; ++mt)
#pragma unroll
                for (int ng = 0; ng < 2; ++ng) {
                    mma16816(sc[mt][ng * 2],     aH[mt], bH[ng][0], bH[ng][2]);
                    mma16816(sc[mt][ng * 2 + 1], aH[mt], bH[ng][1], bH[ng][3]);
                }
        }

        // ---- p = 2^s; pack fp16 A-fragments in registers ----
        uint32_t pA[2][4], pB[2][4];
#pragma unroll
        for (int mt = 0; mt < 2; ++mt)
#pragma unroll
            for (int nf = 0; nf < 4; ++nf) {
                float p0 = fast_ex2(sc[mt][nf][0]);
                float p1 = fast_ex2(sc[mt][nf][1]);
                float p2 = fast_ex2(sc[mt][nf][2]);
                float p3 = fast_ex2(sc[mt][nf][3]);
                l_part[mt * 2 + 0] += p0 + p1;
                l_part[mt * 2 + 1] += p2 + p3;
                pA[mt][nf] = pack_h2(p0, p1);
                pB[mt][nf] = pack_h2(p2, p3);
            }

        // ---- O_partial += P V over this warp's 32 keys, all 64 d ----
#pragma unroll
        for (int ksp = 0; ksp < 2; ++ksp) {
            const int uu = 2 * (wn * 2 + ksp) + (lane >> 4);
            uint32_t bV[4][4];
#pragma unroll
            for (int g = 0; g < 4; ++g)
                ldm4(bV[g], stg + 8192 + SWZ128((g * 16 + rr) * 128 + uu * 16));
#pragma unroll
            for (int mt = 0; mt < 2; ++mt) {
                uint32_t aP[4] = {pA[mt][2 * ksp], pB[mt][2 * ksp],
                                  pA[mt][2 * ksp + 1], pB[mt][2 * ksp + 1]};
#pragma unroll
                for (int g = 0; g < 4; ++g) {
                    mma16816(oc[mt][2 * g],     aP, bV[g][0], bV[g][2]);
                    mma16816(oc[mt][2 * g + 1], aP, bV[g][1], bV[g][3]);
                }
            }
        }

        // stage kb fully consumed; wait for kb+1 data and make write-safe
        if (kb + 1 < SEQ / 64) {
            asm volatile("cp.async.wait_group 0;");
            __syncthreads();
        }
    }
#undef KVPRE

    // ---- reduce l across the 4 lanes of each row-group ----
#pragma unroll
    for (int j = 0; j < 4; ++j) {
        l_part[j] += __shfl_xor_sync(0xFFFFFFFF, l_part[j], 1);
        l_part[j] += __shfl_xor_sync(0xFFFFFFFF, l_part[j], 2);
    }
    if ((lane & 3) == 0) {
#pragma unroll
        for (int mt = 0; mt < 2; ++mt)
#pragma unroll
            for (int half = 0; half < 2; ++half) {
                int r = wm * 32 + mt * 16 + (lane >> 2) + half * 8;
                atomicAdd((float*)(smem + FLSM + r * 4), l_part[mt * 2 + half]);
            }
    }
    __syncthreads();   // all PV done; Q area now dead -> O reduce buffer (32 KB)

    if (wn == 1) {
#pragma unroll
        for (int mt = 0; mt < 2; ++mt) {
            int row = wm * 32 + mt * 16 + (lane >> 2);
#pragma unroll
            for (int nf = 0; nf < 8; ++nf) {
                int col = nf * 8 + (lane & 3) * 2;
                *(float2*)(smem + (row * 64 + col) * 4) =
                    make_float2(oc[mt][nf][0], oc[mt][nf][1]);
                *(float2*)(smem + ((row + 8) * 64 + col) * 4) =
                    make_float2(oc[mt][nf][2], oc[mt][nf][3]);
            }
        }
    }
    __syncthreads();

    if (wn == 0) {
#pragma unroll
        for (int mt = 0; mt < 2; ++mt)
#pragma unroll
            for (int half = 0; half < 2; ++half) {
                int r = wm * 32 + mt * 16 + (lane >> 2) + half * 8;
                float inv = 1.f / *(float*)(smem + FLSM + r * 4);
                size_t mrow = (size_t)(b * SEQ + s0 + r) * EMB;
#pragma unroll
                for (int nf = 0; nf < 8; ++nf) {
                    int col = nf * 8 + (lane & 3) * 2;
                    float2 part = *(float2*)(smem + (r * 64 + col) * 4);
                    float v0 = (oc[mt][nf][half * 2]     + part.x) * inv;
                    float v1 = (oc[mt][nf][half * 2 + 1] + part.y) * inv;
                    *(uint32_t*)&g_ah[mrow + h * HD + col] = pack_h2(v0, v1);
                }
            }
    }
}

// ---------------------------------------------------------------------------
// Launch
// ---------------------------------------------------------------------------
extern "C" void kernel_launch(void* const* d_in, const int* in_sizes, int n_in,
                              void* d_out, int out_size)
{
    const float* query = (const float*)d_in[0];
    const float* xi    = (const float*)d_in[1];
    const float* Wq    = (const float*)d_in[2];
    const float* bq    = (const float*)d_in[3];
    const float* Wk    = (const float*)d_in[4];
    const float* bk    = (const float*)d_in[5];
    const float* Wv    = (const float*)d_in[6];
    const float* bv    = (const float*)d_in[7];
    const float* Wo    = (const float*)d_in[8];
    const float* bo    = (const float*)d_in[9];
    const float* ew1   = (const float*)d_in[10];
    const float* eb1   = (const float*)d_in[11];
    const float* lng   = (const float*)d_in[12];
    const float* lnb   = (const float*)d_in[13];
    const float* ew2   = (const float*)d_in[14];
    const float* eb2   = (const float*)d_in[15];
    const float* gate  = (const float*)d_in[16];
    float* out = (float*)d_out;

    // Idempotent, capture-safe, no static guard (harness rule).
    cudaFuncSetAttribute(gemm_mma, cudaFuncAttributeMaxDynamicSharedMemorySize, GEMM_SMEM);
    cudaFuncSetAttribute(flash_tc, cudaFuncAttributeMaxDynamicSharedMemorySize, FLASH_SMEM);

    int nX = M_TOT * EMB;
    __half *xh, *ah, *w2;
    cudaGetSymbolAddress((void**)&xh, g_xh);
    cudaGetSymbolAddress((void**)&ah, g_ah);
    cudaGetSymbolAddress((void**)&w2, g_w2);

    dim3 wgrid(EMB / 32, EMB / 32, 4);
    dim3 wblk(32, 8);
    dim3 gq(EMB / TN, M_TOT / TM, 3);    // QKV fused
    dim3 go(EMB / TN, M_TOT / TM, 1);    // O

    adapt_kernel<<<1, 32>>>(xi, ew1, eb1, lng, lnb, ew2, eb2, gate);
    half_kernel<<<nX / 1024, 256>>>((const float4*)query, (uint2*)xh, nX / 4);
    wsplit2_all<<<wgrid, wblk>>>(Wq, Wk, Wv, Wo, w2);
    gemm_mma<<<gq, 256, GEMM_SMEM>>>(xh, w2, bq, bk, bv, bo, out, 0);
    flash_tc<<<dim3(SEQ / 128, NH, BATCH), 256, FLASH_SMEM>>>();
    gemm_mma<<<go, 256, GEMM_SMEM>>>(ah, w2, bq, bk, bv, bo, out, 3);
}